// round 7
// baseline (speedup 1.0000x reference)
#include <cuda_runtime.h>
#include <math.h>

#define NIN   12
#define NOUT  4
#define NHID  512
#define NU    40
#define NB    108
#define NINEQ 148
#define BATCH 4096
#define IPM_ITERS 20
#define SIGMA 0.1f
#define BIGF  1000000000.0f
#define EPSF  0.0001f

#define WPB   7                 // warps per block
#define PPW   2                 // problems per warp (packed f32x2)
#define PPC   (WPB * PPW)       // 14
#define NTH   (32 * WPB)        // 224
#define GRID  ((BATCH + PPC - 1) / PPC)   // 293

// shared layout (floats)
#define SQ_OFF  0               // 40*44 = 1760 (scalar Q)
#define B2_OFF  1760            // 108 rows * 42 u64 * 2 floats = 9072 (duplicated B)
#define B2_STRIDE 42            // u64 units per row
#define SH_OFF  10832           // 148 floats
#define PR_OFF  10984           // 16B aligned (43936 B)

// per-pair packed layout (u64 units)
#define H2_OFF   0              // 820 packed lower triangle
#define D2_OFF   820            // 148
#define V2_OFF   968            // 148
#define U2_OFF   1116           // 40
#define RHS2_OFF 1156           // 40 (du overlays rhs)
#define LDI2_OFF 1196           // 40
#define PSTRIDE_U64 1240

#define SMEM_FLOATS (PR_OFF + WPB * PSTRIDE_U64 * 2)   // 10984 + 17360 = 28344
#define SMEM_BYTES  (SMEM_FLOATS * 4)                  // 113376

typedef unsigned long long u64;

__device__ __forceinline__ u64 pk2(float lo, float hi) {
    u64 r; asm("mov.b64 %0,{%1,%2};" : "=l"(r) : "f"(lo), "f"(hi)); return r;
}
__device__ __forceinline__ void upk2(u64 v, float& lo, float& hi) {
    asm("mov.b64 {%0,%1},%2;" : "=f"(lo), "=f"(hi) : "l"(v));
}
__device__ __forceinline__ u64 rep2(float x) { return pk2(x, x); }
__device__ __forceinline__ u64 fma2(u64 a, u64 b, u64 c) {
    u64 d; asm("fma.rn.f32x2 %0,%1,%2,%3;" : "=l"(d) : "l"(a), "l"(b), "l"(c)); return d;
}
__device__ __forceinline__ u64 mul2(u64 a, u64 b) {
    u64 d; asm("mul.rn.f32x2 %0,%1,%2;" : "=l"(d) : "l"(a), "l"(b)); return d;
}
__device__ __forceinline__ u64 add2(u64 a, u64 b) {
    u64 d; asm("add.rn.f32x2 %0,%1,%2;" : "=l"(d) : "l"(a), "l"(b)); return d;
}
__device__ __forceinline__ u64 neg2(u64 a) { return a ^ 0x8000000080000000ULL; }

__device__ float g_Q[NU * NU];
__device__ float g_B[NB * NU];
__device__ float g_h[NINEQ];
__device__ float g_p[BATCH * NU];

__device__ __forceinline__ float lrelu(float x) { return x > 0.f ? x : 0.01f * x; }
__device__ __forceinline__ int toff(int r) { return (r * (r + 1)) >> 1; }

// ================= setup =================
__global__ void setup_kernel(const float* __restrict__ L, const float* __restrict__ LP,
                             const float* __restrict__ LR, const float* __restrict__ A,
                             const float* __restrict__ Bm, const float* __restrict__ u0,
                             const float* __restrict__ s0) {
    __shared__ float sQx[144], sP[144], sR[16], sBp[9 * 48];
    __shared__ float sBh[NB * NU];
    __shared__ float sM[NB * NU];
    int tid = threadIdx.x;
    const int NTs = 128;

    for (int idx = tid; idx < 144; idx += NTs) {
        int i = idx / 12, j = idx % 12;
        int mn = i < j ? i : j;
        float a = 0.f, b = 0.f;
        for (int k = 0; k <= mn; k++) {
            a += L[i * 12 + k] * L[j * 12 + k];
            b += LP[i * 12 + k] * LP[j * 12 + k];
        }
        sQx[idx] = a + (i == j ? EPSF : 0.f);
        sP[idx]  = b + (i == j ? EPSF : 0.f);
    }
    for (int idx = tid; idx < 16; idx += NTs) {
        int i = idx / 4, j = idx % 4;
        int mn = i < j ? i : j;
        float a = 0.f;
        for (int k = 0; k <= mn; k++) a += LR[i * 4 + k] * LR[j * 4 + k];
        sR[idx] = a + (i == j ? EPSF : 0.f);
    }
    if (tid < 48) sBp[tid] = Bm[tid];
    __syncthreads();

    for (int m = 1; m < 9; m++) {
        if (tid < 48) {
            int i = tid / 4, o = tid % 4;
            float v = 0.f;
            for (int k = 0; k < 12; k++) v += A[i * 12 + k] * sBp[(m - 1) * 48 + k * 4 + o];
            sBp[m * 48 + tid] = v;
        }
        __syncthreads();
    }

    for (int idx = tid; idx < NB * NU; idx += NTs) {
        int row = idx / NU, col = idx % NU;
        int rb = row / 12, i = row % 12, cb = col / 4, o = col % 4;
        float v = (cb <= rb) ? sBp[(rb - cb) * 48 + i * 4 + o] : 0.f;
        sBh[idx] = v;
        g_B[idx] = v;
    }
    __syncthreads();

    for (int idx = tid; idx < NB * NU; idx += NTs) {
        int row = idx / NU, col = idx % NU;
        int rb = row / 12, i = row % 12;
        const float* Qd = (rb < 8) ? sQx : sP;
        float a = 0.f;
        for (int k = 0; k < 12; k++) a += Qd[i * 12 + k] * sBh[(rb * 12 + k) * NU + col];
        sM[idx] = a;
    }
    __syncthreads();

    for (int idx = tid; idx < NU * NU; idx += NTs) {
        int a_ = idx / NU, b_ = idx % NU;
        float v = (a_ / 4 == b_ / 4) ? sR[(a_ % 4) * 4 + (b_ % 4)] : 0.f;
        for (int r = 0; r < NB; r++) v += sBh[r * NU + a_] * sM[r * NU + b_];
        g_Q[idx] = v;
    }

    for (int j = tid; j < NINEQ; j += NTs) {
        float v = s0[j];
        if (j < NU) v += u0[j];
        else {
            for (int i = 0; i < NU; i++) v += sBh[(j - NU) * NU + i] * u0[i];
        }
        g_h[j] = v;
    }
}

// ================= MLP =================
__global__ void mlp_kernel(const float* __restrict__ x, const float* __restrict__ W1,
                           const float* __restrict__ b1, const float* __restrict__ W2,
                           const float* __restrict__ b2) {
    __shared__ float hbuf[4][NHID];
    int warp = threadIdx.x >> 5, lane = threadIdx.x & 31;
    int row = blockIdx.x * 4 + warp;

    float xr[NIN];
#pragma unroll
    for (int c = 0; c < NIN; c++) xr[c] = x[row * NIN + c];

#pragma unroll
    for (int t = 0; t < NHID / 32; t++) {
        int j = lane + 32 * t;
        const float* w = W1 + j * NIN;
        float acc = b1[j];
#pragma unroll
        for (int c = 0; c < NIN; c++) acc += w[c] * xr[c];
        hbuf[warp][j] = lrelu(acc);
    }
    __syncwarp();

    for (int k = 0; k < NU; k++) {
        const float* w = W2 + k * NHID;
        float acc = 0.f;
#pragma unroll
        for (int t = 0; t < NHID / 32; t++) {
            int j = lane + 32 * t;
            acc += w[j] * hbuf[warp][j];
        }
#pragma unroll
        for (int o = 16; o; o >>= 1) acc += __shfl_xor_sync(0xffffffffu, acc, o);
        if (lane == 0) g_p[row * NU + k] = lrelu(acc + b2[k]);
    }
}

// ================= IPM: two problems per warp, f32x2 + duplicated B =================
__global__ void __launch_bounds__(NTH, 2) ipm_kernel(float* __restrict__ out) {
    extern __shared__ float sm[];
    float* sQ  = sm + SQ_OFF;    // stride 44 (scalar)
    u64*   B2  = (u64*)(sm + B2_OFF);
    float* sh_ = sm + SH_OFF;

    int tid = threadIdx.x;
    int lane = tid & 31, wid = tid >> 5;

    for (int idx = tid; idx < NU * NU; idx += NTH) sQ[(idx / NU) * 44 + idx % NU] = g_Q[idx];
    for (int idx = tid; idx < NB * NU; idx += NTH) {
        float v = g_B[idx];
        B2[(idx / NU) * B2_STRIDE + (idx % NU)] = pk2(v, v);
    }
    for (int idx = tid; idx < NINEQ; idx += NTH) sh_[idx] = g_h[idx];
    __syncthreads();

    int pb = blockIdx.x * PPC + wid * PPW;
    if (pb >= BATCH) return;   // tail warps

    u64* PR = (u64*)(sm + PR_OFF) + wid * PSTRIDE_U64;
    u64* pH2  = PR + H2_OFF;
    u64* pD2  = PR + D2_OFF;
    u64* pV2  = PR + V2_OFF;
    u64* pU2  = PR + U2_OFF;
    u64* pR2  = PR + RHS2_OFF;
    u64* pDU2 = PR + RHS2_OFF;   // du overlays rhs
    u64* pLi2 = PR + LDI2_OFF;

    // p in registers
    u64 rPl = pk2(g_p[pb * NU + lane], g_p[(pb + 1) * NU + lane]);           // valid lane<32
    u64 rPh = (lane < 8) ? pk2(g_p[pb * NU + 32 + lane], g_p[(pb + 1) * NU + 32 + lane]) : 0ULL;
    if (lane < 32) pU2[lane] = 0ULL;
    if (lane < 8)  pU2[32 + lane] = 0ULL;

    // scalar per-lane state
    float rs0[5], rs1[5], rl0[5], rl1[5], rp0[5], rp1[5];
#pragma unroll
    for (int t = 0; t < 5; t++) { rs0[t] = rs1[t] = rl0[t] = rl1[t] = 1.f; }
    float mu0 = 1.0f, mu1 = 1.0f;

    // H 4x4 block-pair assignment (25 pairs + 5 singles, lanes 30,31 idle)
    int bi = 0, bkA = 0, bkB = 0;
    bool hasB = false, active = false;
    {
        int idx = 0;
        for (int r = 0; r < 10; r++) {
            int np = (r + 1) / 2;
            for (int q = 0; q < np; q++) {
                if (idx == lane) { bi = r; bkA = 2 * q; bkB = 2 * q + 1; hasB = true; active = true; }
                idx++;
            }
        }
        for (int r = 0; r < 10; r += 2) {
            if (idx == lane) { bi = r; bkA = r; bkB = r; hasB = false; active = true; }
            idx++;
        }
    }
    bool diagA = (bkA == bi);
    bool diagB = (bkB == bi);

    __syncwarp();

    for (int it = 0; it < IPM_ITERS; it++) {
        // ---- S0: d, rp, v ----
#pragma unroll
        for (int t = 0; t < 5; t++) {
            int j = lane + 32 * t;
            if (j < NINEQ) {
                float A0, A1;
                if (j < NU) upk2(pU2[j], A0, A1);
                else {
                    const ulonglong2* br2 = (const ulonglong2*)(B2 + (j - NU) * B2_STRIDE);
                    const ulonglong2* u2  = (const ulonglong2*)pU2;
                    u64 acc = 0ULL;
#pragma unroll
                    for (int q = 0; q < 20; q++) {
                        ulonglong2 bv = br2[q];
                        ulonglong2 uv = u2[q];
                        acc = fma2(bv.x, uv.x, acc);
                        acc = fma2(bv.y, uv.y, acc);
                    }
                    upk2(acc, A0, A1);
                }
                float ri0 = 1.0f / rs0[t], ri1 = 1.0f / rs1[t];
                float d0 = rl0[t] * ri0, d1 = rl1[t] * ri1;
                pD2[j] = pk2(d0, d1);
                float hj = sh_[j];
                A0 += rs0[t] - hj;  A1 += rs1[t] - hj;
                rp0[t] = A0;  rp1[t] = A1;
                float v0 = SIGMA * mu0 * ri0 + d0 * A0;
                float v1 = SIGMA * mu1 * ri1 + d1 * A1;
                pV2[j] = pk2(v0, v1);
            }
        }
        __syncwarp();

        // ---- S1: H = Q + diag(d) + B^T diag(d) B  (packed, dup-B) ----
        {
            u64 acc0[4][4], acc1[4][4];
#pragma unroll
            for (int a = 0; a < 4; a++) {
                float4 v0 = *(const float4*)(sQ + (4 * bi + a) * 44 + 4 * bkA);
                acc0[a][0] = rep2(v0.x); acc0[a][1] = rep2(v0.y);
                acc0[a][2] = rep2(v0.z); acc0[a][3] = rep2(v0.w);
                float4 v1 = *(const float4*)(sQ + (4 * bi + a) * 44 + 4 * bkB);
                acc1[a][0] = rep2(v1.x); acc1[a][1] = rep2(v1.y);
                acc1[a][2] = rep2(v1.z); acc1[a][3] = rep2(v1.w);
            }
            if (diagA) {
#pragma unroll
                for (int a = 0; a < 4; a++) acc0[a][a] = add2(acc0[a][a], pD2[4 * bi + a]);
            }
            if (diagB) {
#pragma unroll
                for (int a = 0; a < 4; a++) acc1[a][a] = add2(acc1[a][a], pD2[4 * bi + a]);
            }
#pragma unroll 2
            for (int j = 0; j < NB; j++) {
                u64 dp = pD2[NU + j];
                const u64* b2r = B2 + j * B2_STRIDE;
                ulonglong2 ga01 = *(const ulonglong2*)(b2r + 4 * bi);
                ulonglong2 ga23 = *(const ulonglong2*)(b2r + 4 * bi + 2);
                u64 sa[4];
                sa[0] = mul2(dp, ga01.x); sa[1] = mul2(dp, ga01.y);
                sa[2] = mul2(dp, ga23.x); sa[3] = mul2(dp, ga23.y);
                ulonglong2 rA01 = *(const ulonglong2*)(b2r + 4 * bkA);
                ulonglong2 rA23 = *(const ulonglong2*)(b2r + 4 * bkA + 2);
                ulonglong2 rB01 = *(const ulonglong2*)(b2r + 4 * bkB);
                ulonglong2 rB23 = *(const ulonglong2*)(b2r + 4 * bkB + 2);
                u64 rb0[4] = {rA01.x, rA01.y, rA23.x, rA23.y};
                u64 rb1[4] = {rB01.x, rB01.y, rB23.x, rB23.y};
#pragma unroll
                for (int a = 0; a < 4; a++)
#pragma unroll
                    for (int c = 0; c < 4; c++) {
                        acc0[a][c] = fma2(sa[a], rb0[c], acc0[a][c]);
                        acc1[a][c] = fma2(sa[a], rb1[c], acc1[a][c]);
                    }
            }
            if (active) {
#pragma unroll
                for (int a = 0; a < 4; a++) {
                    int ob = toff(4 * bi + a);
#pragma unroll
                    for (int c = 0; c < 4; c++)
                        if (!diagA || c <= a) pH2[ob + 4 * bkA + c] = acc0[a][c];
                    if (hasB) {
#pragma unroll
                        for (int c = 0; c < 4; c++)
                            if (!diagB || c <= a) pH2[ob + 4 * bkB + c] = acc1[a][c];
                    }
                }
            }
        }

        // ---- rhs = -(Qu + p + v[:40] + B^T v[40:]) ----
        {
            u64 A0 = add2(rPl, pV2[lane]);
            u64 A1 = (lane < 8) ? add2(rPh, pV2[32 + lane]) : 0ULL;
            const float4* q0 = (const float4*)(sQ + lane * 44);
            const float4* q1 = (const float4*)(sQ + (32 + lane) * 44);
#pragma unroll
            for (int q = 0; q < 10; q++) {
                float4 qv0 = q0[q];
                A0 = fma2(rep2(qv0.x), pU2[4 * q + 0], A0);
                A0 = fma2(rep2(qv0.y), pU2[4 * q + 1], A0);
                A0 = fma2(rep2(qv0.z), pU2[4 * q + 2], A0);
                A0 = fma2(rep2(qv0.w), pU2[4 * q + 3], A0);
                if (lane < 8) {
                    float4 qv1 = q1[q];
                    A1 = fma2(rep2(qv1.x), pU2[4 * q + 0], A1);
                    A1 = fma2(rep2(qv1.y), pU2[4 * q + 1], A1);
                    A1 = fma2(rep2(qv1.z), pU2[4 * q + 2], A1);
                    A1 = fma2(rep2(qv1.w), pU2[4 * q + 3], A1);
                }
            }
#pragma unroll 2
            for (int j = 0; j < NB; j++) {
                const u64* b2r = B2 + j * B2_STRIDE;
                u64 vj = pV2[NU + j];
                A0 = fma2(b2r[lane], vj, A0);
                if (lane < 8) A1 = fma2(b2r[32 + lane], vj, A1);
            }
            pR2[lane] = neg2(A0);
            if (lane < 8) pR2[32 + lane] = neg2(A1);
        }
        __syncwarp();

        // ---- S3: blocked Cholesky (panel=8), packed ----
        for (int pp = 0; pp < 5; pp++) {
            int k0 = 8 * pp;
            for (int kk = 0; kk < 8; kk++) {
                int k = k0 + kk;
                int ok = toff(k);
                float h0, h1;
                upk2(pH2[ok + k], h0, h1);
                float i0 = rsqrtf(h0); i0 = i0 * (1.5f - 0.5f * h0 * i0 * i0);
                float i1 = rsqrtf(h1); i1 = i1 * (1.5f - 0.5f * h1 * i1 * i1);
                u64 ip = pk2(i0, i1);
                if (lane == 0) pLi2[k] = ip;
                int r0 = k + 1 + lane, r1 = r0 + 32;
                int or0 = toff(r0), or1 = toff(r1);
                u64 v0 = 0ULL, v1 = 0ULL;
                if (r0 < NU) { v0 = mul2(pH2[or0 + k], ip); pH2[or0 + k] = v0; }
                if (r1 < NU) { v1 = mul2(pH2[or1 + k], ip); pH2[or1 + k] = v1; }
                __syncwarp();
                for (int j = k + 1; j < k0 + 8; j++) {
                    u64 m = __shfl_sync(0xffffffffu, v0, j - k - 1);
                    u64 nm = neg2(m);
                    if (r0 < NU && r0 >= j) pH2[or0 + j] = fma2(nm, v0, pH2[or0 + j]);
                    if (r1 < NU)            pH2[or1 + j] = fma2(nm, v1, pH2[or1 + j]);
                }
                __syncwarp();
            }
            if (pp < 4) {
                int base = k0 + 8;
                int nbk = (NU - base) >> 2;
                int cnt = nbk * (nbk + 1) / 2;
                for (int bb = lane; bb < cnt; bb += 32) {
                    int t = bb, r = 0;
                    while (t > r) { t -= r + 1; r++; }
                    int c = t;
                    int ri = base + 4 * r, ci = base + 4 * c;
                    bool diag = (r == c);
                    int oR[4], oC[4];
                    oR[0] = toff(ri);
                    oR[1] = oR[0] + ri + 1; oR[2] = oR[1] + ri + 2; oR[3] = oR[2] + ri + 3;
                    oC[0] = toff(ci);
                    oC[1] = oC[0] + ci + 1; oC[2] = oC[1] + ci + 2; oC[3] = oC[2] + ci + 3;
                    u64 a2[4][4];
#pragma unroll
                    for (int a = 0; a < 4; a++)
#pragma unroll
                        for (int cb = 0; cb < 4; cb++)
                            a2[a][cb] = pH2[oR[a] + ci + cb];
#pragma unroll
                    for (int kk = 0; kk < 8; kk++) {
                        u64 nla[4], lb[4];
#pragma unroll
                        for (int a = 0; a < 4; a++) nla[a] = neg2(pH2[oR[a] + k0 + kk]);
#pragma unroll
                        for (int cb = 0; cb < 4; cb++) lb[cb] = pH2[oC[cb] + k0 + kk];
#pragma unroll
                        for (int a = 0; a < 4; a++)
#pragma unroll
                            for (int cb = 0; cb < 4; cb++)
                                a2[a][cb] = fma2(nla[a], lb[cb], a2[a][cb]);
                    }
#pragma unroll
                    for (int a = 0; a < 4; a++)
#pragma unroll
                        for (int cb = 0; cb < 4; cb++)
                            if (!diag || cb <= a) pH2[oR[a] + ci + cb] = a2[a][cb];
                }
                __syncwarp();
            }
        }

        // ---- triangular solves (packed); result lands in pR2 (= pDU2) ----
        {
            int offL0 = toff(lane);
            int offL1 = toff(32 + lane);
            u64 a0 = pR2[lane];
            u64 a1 = (lane < 8) ? pR2[32 + lane] : 0ULL;
            for (int k = 0; k < NU; k++) {
                u64 src = (k < 32) ? a0 : a1;
                u64 y = mul2(__shfl_sync(0xffffffffu, src, k & 31), pLi2[k]);
                if (k < 32) { if (lane == k) a0 = y; }
                else        { if (lane == k - 32) a1 = y; }
                u64 ny = neg2(y);
                if (lane > k) a0 = fma2(pH2[offL0 + k], ny, a0);
                if (lane < 8 && 32 + lane > k) a1 = fma2(pH2[offL1 + k], ny, a1);
            }
            int offk = toff(NU - 1);
            for (int k = NU - 1; k >= 0; k--) {
                u64 src = (k < 32) ? a0 : a1;
                u64 x = mul2(__shfl_sync(0xffffffffu, src, k & 31), pLi2[k]);
                if (k < 32) { if (lane == k) a0 = x; }
                else        { if (lane == k - 32) a1 = x; }
                u64 nx = neg2(x);
                if (lane < k) a0 = fma2(pH2[offk + lane], nx, a0);
                if (lane < 8 && 32 + lane < k) a1 = fma2(pH2[offk + 32 + lane], nx, a1);
                offk -= k;
            }
            pDU2[lane] = a0;
            if (lane < 8) pDU2[32 + lane] = a1;
        }
        __syncwarp();

        // ---- S4: ds, dlam, alpha ----
        float am0 = BIGF, am1 = BIGF;
        float ds0a[5], ds1a[5], dl0a[5], dl1a[5];
#pragma unroll
        for (int t = 0; t < 5; t++) {
            int j = lane + 32 * t;
            if (j < NINEQ) {
                u64 g;
                if (j < NU) g = pDU2[j];
                else {
                    const ulonglong2* br2 = (const ulonglong2*)(B2 + (j - NU) * B2_STRIDE);
                    const ulonglong2* d2  = (const ulonglong2*)pDU2;
                    u64 acc = 0ULL;
#pragma unroll
                    for (int q = 0; q < 20; q++) {
                        ulonglong2 bv = br2[q];
                        ulonglong2 dv = d2[q];
                        acc = fma2(bv.x, dv.x, acc);
                        acc = fma2(bv.y, dv.y, acc);
                    }
                    g = acc;
                }
                float g0, g1, d0, d1, v0, v1;
                upk2(g, g0, g1);
                upk2(pD2[j], d0, d1);
                upk2(pV2[j], v0, v1);
                float ds0 = -rp0[t] - g0, ds1 = -rp1[t] - g1;
                float dl0 = v0 - rl0[t] + d0 * g0;
                float dl1 = v1 - rl1[t] + d1 * g1;
                ds0a[t] = ds0; ds1a[t] = ds1; dl0a[t] = dl0; dl1a[t] = dl1;
                float q0 = (ds0 < 0.f) ? -rs0[t] / ds0 : BIGF;
                float q1 = (dl0 < 0.f) ? -rl0[t] / dl0 : BIGF;
                am0 = fminf(am0, fminf(q0, q1));
                float q2 = (ds1 < 0.f) ? -rs1[t] / ds1 : BIGF;
                float q3 = (dl1 < 0.f) ? -rl1[t] / dl1 : BIGF;
                am1 = fminf(am1, fminf(q2, q3));
            }
        }
#pragma unroll
        for (int o = 16; o; o >>= 1) {
            am0 = fminf(am0, __shfl_xor_sync(0xffffffffu, am0, o));
            am1 = fminf(am1, __shfl_xor_sync(0xffffffffu, am1, o));
        }
        float al0 = fminf(1.0f, 0.99f * am0);
        float al1 = fminf(1.0f, 0.99f * am1);

        // ---- S5: update + mu ----
        float ls0 = 0.f, ls1 = 0.f;
#pragma unroll
        for (int t = 0; t < 5; t++) {
            int j = lane + 32 * t;
            if (j < NINEQ) {
                rs0[t] += al0 * ds0a[t];  rl0[t] += al0 * dl0a[t];  ls0 += rs0[t] * rl0[t];
                rs1[t] += al1 * ds1a[t];  rl1[t] += al1 * dl1a[t];  ls1 += rs1[t] * rl1[t];
            }
        }
#pragma unroll
        for (int o = 16; o; o >>= 1) {
            ls0 += __shfl_xor_sync(0xffffffffu, ls0, o);
            ls1 += __shfl_xor_sync(0xffffffffu, ls1, o);
        }
        mu0 = ls0 * (1.0f / 148.0f);
        mu1 = ls1 * (1.0f / 148.0f);

        u64 alp = pk2(al0, al1);
        pU2[lane] = fma2(alp, pDU2[lane], pU2[lane]);
        if (lane < 8) pU2[32 + lane] = fma2(alp, pDU2[32 + lane], pU2[32 + lane]);
        __syncwarp();
    }

    // ---- output: Q_value = 0.5 u'Qu + p'u ; u0 ----
    {
        const float4* q0 = (const float4*)(sQ + lane * 44);
        const float4* q1 = (const float4*)(sQ + (32 + lane) * 44);
        u64 qu0 = 0ULL, qu1 = 0ULL;
#pragma unroll
        for (int q = 0; q < 10; q++) {
            float4 qv0 = q0[q];
            qu0 = fma2(rep2(qv0.x), pU2[4 * q + 0], qu0);
            qu0 = fma2(rep2(qv0.y), pU2[4 * q + 1], qu0);
            qu0 = fma2(rep2(qv0.z), pU2[4 * q + 2], qu0);
            qu0 = fma2(rep2(qv0.w), pU2[4 * q + 3], qu0);
            if (lane < 8) {
                float4 qv1 = q1[q];
                qu1 = fma2(rep2(qv1.x), pU2[4 * q + 0], qu1);
                qu1 = fma2(rep2(qv1.y), pU2[4 * q + 1], qu1);
                qu1 = fma2(rep2(qv1.z), pU2[4 * q + 2], qu1);
                qu1 = fma2(rep2(qv1.w), pU2[4 * q + 3], qu1);
            }
        }
        float qa0, qa1, ua0, ua1, pa0, pa1;
        upk2(qu0, qa0, qa1);
        upk2(pU2[lane], ua0, ua1);
        upk2(rPl, pa0, pa1);
        float part0 = ua0 * (0.5f * qa0 + pa0);
        float part1 = ua1 * (0.5f * qa1 + pa1);
        if (lane < 8) {
            float qb0, qb1, ub0, ub1, pb0, pb1;
            upk2(qu1, qb0, qb1);
            upk2(pU2[32 + lane], ub0, ub1);
            upk2(rPh, pb0, pb1);
            part0 += ub0 * (0.5f * qb0 + pb0);
            part1 += ub1 * (0.5f * qb1 + pb1);
        }
#pragma unroll
        for (int o = 16; o; o >>= 1) {
            part0 += __shfl_xor_sync(0xffffffffu, part0, o);
            part1 += __shfl_xor_sync(0xffffffffu, part1, o);
        }
        if (lane == 0) {
            float u00, u01;
            upk2(pU2[0], u00, u01);
            out[pb] = part0;
            out[pb + 1] = part1;
            out[BATCH + pb] = u00;
            out[BATCH + pb + 1] = u01;
        }
    }
}

// ================= launch =================
extern "C" void kernel_launch(void* const* d_in, const int* in_sizes, int n_in,
                              void* d_out, int out_size) {
    const float* x  = (const float*)d_in[0];
    const float* W1 = (const float*)d_in[1];
    const float* b1 = (const float*)d_in[2];
    const float* W2 = (const float*)d_in[3];
    const float* b2 = (const float*)d_in[4];
    const float* L  = (const float*)d_in[5];
    const float* LP = (const float*)d_in[6];
    const float* LR = (const float*)d_in[7];
    const float* A  = (const float*)d_in[8];
    const float* Bm = (const float*)d_in[9];
    const float* u0 = (const float*)d_in[10];
    const float* s0 = (const float*)d_in[11];

    cudaFuncSetAttribute(ipm_kernel, cudaFuncAttributeMaxDynamicSharedMemorySize, SMEM_BYTES);

    setup_kernel<<<1, 128>>>(L, LP, LR, A, Bm, u0, s0);
    mlp_kernel<<<BATCH / 4, 128>>>(x, W1, b1, W2, b2);
    ipm_kernel<<<GRID, NTH, SMEM_BYTES>>>((float*)d_out);
}

// round 8
// speedup vs baseline: 1.1368x; 1.1368x over previous
#include <cuda_runtime.h>
#include <math.h>

#define NIN   12
#define NOUT  4
#define NHID  512
#define NU    40
#define NB    108
#define NINEQ 148
#define BATCH 4096
#define IPM_ITERS 20
#define SIGMA 0.1f
#define BIGF  1000000000.0f
#define EPSF  0.0001f

#define WPB   8                 // warps per block
#define PPW   2                 // problems per warp (packed f32x2)
#define PPC   (WPB * PPW)
#define NTH   (32 * WPB)

// shared scalar layout (floats)
#define SQ_OFF 0                // 40*44 = 1760
#define SB_OFF 1760             // 108*44 = 4752
#define SH_OFF 6512             // 148 -> pad to 6672
#define PR_OFF 6672

// per-pair packed layout (u64 units)
#define H2_OFF   0              // 820 packed lower triangle
#define D2_OFF   820            // 148
#define V2_OFF   968            // 148
#define U2_OFF   1116           // 40
#define RHS2_OFF 1156           // 40
#define DU2_OFF  1196           // 40
#define LDI2_OFF 1236           // 40
#define P2_OFF   1276           // 40
#define PSTRIDE_U64 1320

#define SMEM_FLOATS (PR_OFF + WPB * PSTRIDE_U64 * 2)
#define SMEM_BYTES  (SMEM_FLOATS * 4)

typedef unsigned long long u64;

__device__ __forceinline__ u64 pk2(float lo, float hi) {
    u64 r; asm("mov.b64 %0,{%1,%2};" : "=l"(r) : "f"(lo), "f"(hi)); return r;
}
__device__ __forceinline__ void upk2(u64 v, float& lo, float& hi) {
    asm("mov.b64 {%0,%1},%2;" : "=f"(lo), "=f"(hi) : "l"(v));
}
__device__ __forceinline__ u64 rep2(float x) { return pk2(x, x); }
__device__ __forceinline__ u64 fma2(u64 a, u64 b, u64 c) {
    u64 d; asm("fma.rn.f32x2 %0,%1,%2,%3;" : "=l"(d) : "l"(a), "l"(b), "l"(c)); return d;
}
__device__ __forceinline__ u64 mul2(u64 a, u64 b) {
    u64 d; asm("mul.rn.f32x2 %0,%1,%2;" : "=l"(d) : "l"(a), "l"(b)); return d;
}
__device__ __forceinline__ u64 add2(u64 a, u64 b) {
    u64 d; asm("add.rn.f32x2 %0,%1,%2;" : "=l"(d) : "l"(a), "l"(b)); return d;
}
__device__ __forceinline__ u64 neg2(u64 a) { return a ^ 0x8000000080000000ULL; }

__device__ float g_Q[NU * NU];
__device__ float g_B[NB * NU];
__device__ float g_h[NINEQ];
__device__ float g_p[BATCH * NU];

__device__ __forceinline__ float lrelu(float x) { return x > 0.f ? x : 0.01f * x; }
__device__ __forceinline__ int toff(int r) { return (r * (r + 1)) >> 1; }

// ---- H balanced block schedule: per lane up to 4 segments (bi, bk); len = 108-12*bi ----
__constant__ signed char c_bi[32][4] = {
  {0,-1,-1,-1},
  {1,8,-1,-1},{1,8,-1,-1},
  {2,7,-1,-1},{2,7,-1,-1},{2,7,-1,-1},
  {3,6,-1,-1},{3,6,-1,-1},{3,6,-1,-1},{3,6,-1,-1},
  {4,5,-1,-1},{4,5,-1,-1},{4,5,-1,-1},{4,5,-1,-1},{4,5,-1,-1},
  {5,6,8,8},
  {6,6,7,8},
  {7,7,7,7},
  {8,8,8,8},
  {-1,-1,-1,-1},{-1,-1,-1,-1},{-1,-1,-1,-1},{-1,-1,-1,-1},{-1,-1,-1,-1},
  {-1,-1,-1,-1},{-1,-1,-1,-1},{-1,-1,-1,-1},{-1,-1,-1,-1},{-1,-1,-1,-1},
  {-1,-1,-1,-1},{-1,-1,-1,-1},{-1,-1,-1,-1}
};
__constant__ signed char c_bk[32][4] = {
  {0,0,0,0},
  {0,0,0,0},{1,1,0,0},
  {0,0,0,0},{1,1,0,0},{2,2,0,0},
  {0,0,0,0},{1,1,0,0},{2,2,0,0},{3,3,0,0},
  {0,0,0,0},{1,1,0,0},{2,2,0,0},{3,3,0,0},{4,4,0,0},
  {5,4,2,3},
  {5,6,3,4},
  {4,5,6,7},
  {5,6,7,8},
  {0,0,0,0},{0,0,0,0},{0,0,0,0},{0,0,0,0},{0,0,0,0},
  {0,0,0,0},{0,0,0,0},{0,0,0,0},{0,0,0,0},{0,0,0,0},
  {0,0,0,0},{0,0,0,0},{0,0,0,0}
};

// ================= setup =================
__global__ void setup_kernel(const float* __restrict__ L, const float* __restrict__ LP,
                             const float* __restrict__ LR, const float* __restrict__ A,
                             const float* __restrict__ Bm, const float* __restrict__ u0,
                             const float* __restrict__ s0) {
    __shared__ float sQx[144], sP[144], sR[16], sBp[9 * 48];
    __shared__ float sBh[NB * NU];
    __shared__ float sM[NB * NU];
    int tid = threadIdx.x;
    const int NTs = 128;

    for (int idx = tid; idx < 144; idx += NTs) {
        int i = idx / 12, j = idx % 12;
        int mn = i < j ? i : j;
        float a = 0.f, b = 0.f;
        for (int k = 0; k <= mn; k++) {
            a += L[i * 12 + k] * L[j * 12 + k];
            b += LP[i * 12 + k] * LP[j * 12 + k];
        }
        sQx[idx] = a + (i == j ? EPSF : 0.f);
        sP[idx]  = b + (i == j ? EPSF : 0.f);
    }
    for (int idx = tid; idx < 16; idx += NTs) {
        int i = idx / 4, j = idx % 4;
        int mn = i < j ? i : j;
        float a = 0.f;
        for (int k = 0; k <= mn; k++) a += LR[i * 4 + k] * LR[j * 4 + k];
        sR[idx] = a + (i == j ? EPSF : 0.f);
    }
    if (tid < 48) sBp[tid] = Bm[tid];
    __syncthreads();

    for (int m = 1; m < 9; m++) {
        if (tid < 48) {
            int i = tid / 4, o = tid % 4;
            float v = 0.f;
            for (int k = 0; k < 12; k++) v += A[i * 12 + k] * sBp[(m - 1) * 48 + k * 4 + o];
            sBp[m * 48 + tid] = v;
        }
        __syncthreads();
    }

    for (int idx = tid; idx < NB * NU; idx += NTs) {
        int row = idx / NU, col = idx % NU;
        int rb = row / 12, i = row % 12, cb = col / 4, o = col % 4;
        float v = (cb <= rb) ? sBp[(rb - cb) * 48 + i * 4 + o] : 0.f;
        sBh[idx] = v;
        g_B[idx] = v;
    }
    __syncthreads();

    for (int idx = tid; idx < NB * NU; idx += NTs) {
        int row = idx / NU, col = idx % NU;
        int rb = row / 12, i = row % 12;
        const float* Qd = (rb < 8) ? sQx : sP;
        float a = 0.f;
        for (int k = 0; k < 12; k++) a += Qd[i * 12 + k] * sBh[(rb * 12 + k) * NU + col];
        sM[idx] = a;
    }
    __syncthreads();

    for (int idx = tid; idx < NU * NU; idx += NTs) {
        int a_ = idx / NU, b_ = idx % NU;
        float v = (a_ / 4 == b_ / 4) ? sR[(a_ % 4) * 4 + (b_ % 4)] : 0.f;
        for (int r = 0; r < NB; r++) v += sBh[r * NU + a_] * sM[r * NU + b_];
        g_Q[idx] = v;
    }

    for (int j = tid; j < NINEQ; j += NTs) {
        float v = s0[j];
        if (j < NU) v += u0[j];
        else {
            for (int i = 0; i < NU; i++) v += sBh[(j - NU) * NU + i] * u0[i];
        }
        g_h[j] = v;
    }
}

// ================= MLP =================
__global__ void mlp_kernel(const float* __restrict__ x, const float* __restrict__ W1,
                           const float* __restrict__ b1, const float* __restrict__ W2,
                           const float* __restrict__ b2) {
    __shared__ float hbuf[4][NHID];
    int warp = threadIdx.x >> 5, lane = threadIdx.x & 31;
    int row = blockIdx.x * 4 + warp;

    float xr[NIN];
#pragma unroll
    for (int c = 0; c < NIN; c++) xr[c] = x[row * NIN + c];

#pragma unroll
    for (int t = 0; t < NHID / 32; t++) {
        int j = lane + 32 * t;
        const float* w = W1 + j * NIN;
        float acc = b1[j];
#pragma unroll
        for (int c = 0; c < NIN; c++) acc += w[c] * xr[c];
        hbuf[warp][j] = lrelu(acc);
    }
    __syncwarp();

    for (int k = 0; k < NU; k++) {
        const float* w = W2 + k * NHID;
        float acc = 0.f;
#pragma unroll
        for (int t = 0; t < NHID / 32; t++) {
            int j = lane + 32 * t;
            acc += w[j] * hbuf[warp][j];
        }
#pragma unroll
        for (int o = 16; o; o >>= 1) acc += __shfl_xor_sync(0xffffffffu, acc, o);
        if (lane == 0) g_p[row * NU + k] = lrelu(acc + b2[k]);
    }
}

// ================= IPM: two problems per warp, f32x2, sparse-B H =================
__global__ void __launch_bounds__(NTH, 2) ipm_kernel(float* __restrict__ out) {
    extern __shared__ float sm[];
    float* sQ  = sm + SQ_OFF;    // stride 44
    float* sB  = sm + SB_OFF;    // stride 44
    float* sh_ = sm + SH_OFF;

    int tid = threadIdx.x;
    int lane = tid & 31, wid = tid >> 5;

    for (int idx = tid; idx < NU * NU; idx += NTH) sQ[(idx / NU) * 44 + idx % NU] = g_Q[idx];
    for (int idx = tid; idx < NB * NU; idx += NTH) sB[(idx / NU) * 44 + idx % NU] = g_B[idx];
    for (int idx = tid; idx < NINEQ; idx += NTH) sh_[idx] = g_h[idx];
    __syncthreads();

    int pb = blockIdx.x * PPC + wid * PPW;
    u64* PR = (u64*)(sm + PR_OFF) + wid * PSTRIDE_U64;
    u64* pH2  = PR + H2_OFF;
    u64* pD2  = PR + D2_OFF;
    u64* pV2  = PR + V2_OFF;
    u64* pU2  = PR + U2_OFF;
    u64* pR2  = PR + RHS2_OFF;
    u64* pDU2 = PR + DU2_OFF;
    u64* pLi2 = PR + LDI2_OFF;
    u64* pP2  = PR + P2_OFF;

    if (lane < NU) {
        pU2[lane] = 0ULL;
        pP2[lane] = pk2(g_p[pb * NU + lane], g_p[(pb + 1) * NU + lane]);
    }
    if (lane < 8) {
        pU2[32 + lane] = 0ULL;
        pP2[32 + lane] = pk2(g_p[pb * NU + 32 + lane], g_p[(pb + 1) * NU + 32 + lane]);
    }

    // scalar per-lane state
    float rs0[5], rs1[5], rl0[5], rl1[5], rp0[5], rp1[5];
#pragma unroll
    for (int t = 0; t < 5; t++) { rs0[t] = rs1[t] = rl0[t] = rl1[t] = 1.f; }
    float mu0 = 1.0f, mu1 = 1.0f;

    // load H schedule for this lane
    int hb_bi[4], hb_bk[4];
#pragma unroll
    for (int s = 0; s < 4; s++) { hb_bi[s] = c_bi[lane][s]; hb_bk[s] = c_bk[lane][s]; }

    // B-row sparsity bounds per t-group (float4 groups)
    const int QBND1 = 2, QBND2 = 5, QBND3 = 8, QBND4 = 9;

    __syncwarp();

    for (int it = 0; it < IPM_ITERS; it++) {
        // ---- S0: d, rp, v (sparse dots) ----
#pragma unroll
        for (int t = 0; t < 5; t++) {
            int j = lane + 32 * t;
            if (j < NINEQ) {
                float A0, A1;
                if (j < NU) upk2(pU2[j], A0, A1);
                else {
                    const float4* br4 = (const float4*)(sB + (j - NU) * 44);
                    u64 acc = 0ULL;
                    int bnd = (t == 1) ? QBND1 : (t == 2) ? QBND2 : (t == 3) ? QBND3 : QBND4;
#pragma unroll
                    for (int q = 0; q < 9; q++) {
                        if (q >= bnd) break;
                        float4 bv = br4[q];
                        acc = fma2(rep2(bv.x), pU2[4 * q + 0], acc);
                        acc = fma2(rep2(bv.y), pU2[4 * q + 1], acc);
                        acc = fma2(rep2(bv.z), pU2[4 * q + 2], acc);
                        acc = fma2(rep2(bv.w), pU2[4 * q + 3], acc);
                    }
                    upk2(acc, A0, A1);
                }
                float ri0 = 1.0f / rs0[t], ri1 = 1.0f / rs1[t];
                float d0 = rl0[t] * ri0, d1 = rl1[t] * ri1;
                pD2[j] = pk2(d0, d1);
                float hj = sh_[j];
                A0 += rs0[t] - hj;  A1 += rs1[t] - hj;
                rp0[t] = A0;  rp1[t] = A1;
                float v0 = SIGMA * mu0 * ri0 + d0 * A0;
                float v1 = SIGMA * mu1 * ri1 + d1 * A1;
                pV2[j] = pk2(v0, v1);
            }
        }
        __syncwarp();

        // ---- S1: H via balanced sparse block schedule ----
        {
            u64 acc[4][4];
            int s = 0;
            int bis = hb_bi[0];
            bool valid = (bis >= 0);
            int bks = valid ? hb_bk[0] : 0;
            int segEnd = valid ? (108 - 12 * bis) : (1 << 28);
            int jb = valid ? 12 * bis : 0;
            int r4 = 4 * bis, c4b = 4 * bks;
            if (valid) {
#pragma unroll
                for (int a = 0; a < 4; a++) {
                    float4 qv = *(const float4*)(sQ + (r4 + a) * 44 + c4b);
                    acc[a][0] = rep2(qv.x); acc[a][1] = rep2(qv.y);
                    acc[a][2] = rep2(qv.z); acc[a][3] = rep2(qv.w);
                }
                if (bis == bks) {
#pragma unroll
                    for (int a = 0; a < 4; a++) acc[a][a] = add2(acc[a][a], pD2[r4 + a]);
                }
            }
            for (int c = 0; c < 108; c++) {
                if (c == segEnd) {
                    // flush finished block
                    bool dg = (bis == bks);
#pragma unroll
                    for (int a = 0; a < 4; a++) {
                        int ob = toff(r4 + a) + c4b;
#pragma unroll
                        for (int cc = 0; cc < 4; cc++)
                            if (!dg || cc <= a) pH2[ob + cc] = acc[a][cc];
                    }
                    s++;
                    bis = (s < 4) ? hb_bi[s] : -1;
                    valid = (bis >= 0);
                    if (valid) {
                        bks = hb_bk[s];
                        r4 = 4 * bis; c4b = 4 * bks;
                        jb = 12 * bis - c;
                        segEnd = c + (108 - 12 * bis);
#pragma unroll
                        for (int a = 0; a < 4; a++) {
                            float4 qv = *(const float4*)(sQ + (r4 + a) * 44 + c4b);
                            acc[a][0] = rep2(qv.x); acc[a][1] = rep2(qv.y);
                            acc[a][2] = rep2(qv.z); acc[a][3] = rep2(qv.w);
                        }
                        if (bis == bks) {
#pragma unroll
                            for (int a = 0; a < 4; a++) acc[a][a] = add2(acc[a][a], pD2[r4 + a]);
                        }
                    } else segEnd = 1 << 28;
                }
                if (valid) {
                    int j = jb + c;
                    u64 dp = pD2[NU + j];
                    const float* br = sB + j * 44;
                    float4 ga = *(const float4*)(br + r4);
                    float4 gb = *(const float4*)(br + c4b);
                    u64 sa0 = mul2(dp, rep2(ga.x)), sa1 = mul2(dp, rep2(ga.y));
                    u64 sa2 = mul2(dp, rep2(ga.z)), sa3 = mul2(dp, rep2(ga.w));
                    u64 rb0 = rep2(gb.x), rb1 = rep2(gb.y), rb2 = rep2(gb.z), rb3 = rep2(gb.w);
                    acc[0][0] = fma2(sa0, rb0, acc[0][0]); acc[0][1] = fma2(sa0, rb1, acc[0][1]);
                    acc[0][2] = fma2(sa0, rb2, acc[0][2]); acc[0][3] = fma2(sa0, rb3, acc[0][3]);
                    acc[1][0] = fma2(sa1, rb0, acc[1][0]); acc[1][1] = fma2(sa1, rb1, acc[1][1]);
                    acc[1][2] = fma2(sa1, rb2, acc[1][2]); acc[1][3] = fma2(sa1, rb3, acc[1][3]);
                    acc[2][0] = fma2(sa2, rb0, acc[2][0]); acc[2][1] = fma2(sa2, rb1, acc[2][1]);
                    acc[2][2] = fma2(sa2, rb2, acc[2][2]); acc[2][3] = fma2(sa2, rb3, acc[2][3]);
                    acc[3][0] = fma2(sa3, rb0, acc[3][0]); acc[3][1] = fma2(sa3, rb1, acc[3][1]);
                    acc[3][2] = fma2(sa3, rb2, acc[3][2]); acc[3][3] = fma2(sa3, rb3, acc[3][3]);
                }
            }
            if (valid) {
                bool dg = (bis == bks);
#pragma unroll
                for (int a = 0; a < 4; a++) {
                    int ob = toff(r4 + a) + c4b;
#pragma unroll
                    for (int cc = 0; cc < 4; cc++)
                        if (!dg || cc <= a) pH2[ob + cc] = acc[a][cc];
                }
            }
            // row-9 blocks: H(9,k) = Q block (+ diag d for k==9); no B contribution
            if (lane >= 19 && lane < 29) {
                int k9 = lane - 19;
                bool dg = (k9 == 9);
#pragma unroll
                for (int a = 0; a < 4; a++) {
                    float4 qv = *(const float4*)(sQ + (36 + a) * 44 + 4 * k9);
                    u64 vals[4] = {rep2(qv.x), rep2(qv.y), rep2(qv.z), rep2(qv.w)};
                    if (dg) vals[a] = add2(vals[a], pD2[36 + a]);
                    int ob = toff(36 + a) + 4 * k9;
#pragma unroll
                    for (int cc = 0; cc < 4; cc++)
                        if (!dg || cc <= a) pH2[ob + cc] = vals[cc];
                }
            }
        }

        // ---- rhs = -(Qu + p + v[:40] + B^T v[40:]) ----
        {
            u64 A0 = add2(pP2[lane], pV2[lane]);
            u64 A1 = (lane < 8) ? add2(pP2[32 + lane], pV2[32 + lane]) : 0ULL;
            const float4* q0 = (const float4*)(sQ + lane * 44);
            const float4* q1 = (const float4*)(sQ + (32 + lane) * 44);
#pragma unroll
            for (int q = 0; q < 10; q++) {
                float4 qv0 = q0[q];
                A0 = fma2(rep2(qv0.x), pU2[4 * q + 0], A0);
                A0 = fma2(rep2(qv0.y), pU2[4 * q + 1], A0);
                A0 = fma2(rep2(qv0.z), pU2[4 * q + 2], A0);
                A0 = fma2(rep2(qv0.w), pU2[4 * q + 3], A0);
                if (lane < 8) {
                    float4 qv1 = q1[q];
                    A1 = fma2(rep2(qv1.x), pU2[4 * q + 0], A1);
                    A1 = fma2(rep2(qv1.y), pU2[4 * q + 1], A1);
                    A1 = fma2(rep2(qv1.z), pU2[4 * q + 2], A1);
                    A1 = fma2(rep2(qv1.w), pU2[4 * q + 3], A1);
                }
            }
#pragma unroll 2
            for (int j = 0; j < NB; j++) {
                const float* br = sB + j * 44;
                A0 = fma2(rep2(br[lane]), pV2[NU + j], A0);
            }
            // cols 32-35 need j >= 96 only; cols 36-39 are zero in B
            if (lane < 8) {
#pragma unroll
                for (int j = 96; j < NB; j++) {
                    const float* br = sB + j * 44;
                    A1 = fma2(rep2(br[32 + lane]), pV2[NU + j], A1);
                }
            }
            pR2[lane] = neg2(A0);
            if (lane < 8) pR2[32 + lane] = neg2(A1);
        }
        __syncwarp();

        // ---- S3: blocked Cholesky (panel=8), packed ----
        for (int pp = 0; pp < 5; pp++) {
            int k0 = 8 * pp;
            for (int kk = 0; kk < 8; kk++) {
                int k = k0 + kk;
                int ok = toff(k);
                float h0, h1;
                upk2(pH2[ok + k], h0, h1);
                float i0 = rsqrtf(h0); i0 = i0 * (1.5f - 0.5f * h0 * i0 * i0);
                float i1 = rsqrtf(h1); i1 = i1 * (1.5f - 0.5f * h1 * i1 * i1);
                u64 ip = pk2(i0, i1);
                if (lane == 0) pLi2[k] = ip;
                int r0 = k + 1 + lane, r1 = r0 + 32;
                int or0 = toff(r0), or1 = toff(r1);
                u64 v0 = 0ULL, v1 = 0ULL;
                if (r0 < NU) { v0 = mul2(pH2[or0 + k], ip); pH2[or0 + k] = v0; }
                if (r1 < NU) { v1 = mul2(pH2[or1 + k], ip); pH2[or1 + k] = v1; }
                __syncwarp();
                for (int j = k + 1; j < k0 + 8; j++) {
                    u64 m = __shfl_sync(0xffffffffu, v0, j - k - 1);
                    u64 nm = neg2(m);
                    if (r0 < NU && r0 >= j) pH2[or0 + j] = fma2(nm, v0, pH2[or0 + j]);
                    if (r1 < NU)            pH2[or1 + j] = fma2(nm, v1, pH2[or1 + j]);
                }
                __syncwarp();
            }
            if (pp < 4) {
                int base = k0 + 8;
                int nbk = (NU - base) >> 2;
                int cnt = nbk * (nbk + 1) / 2;
                for (int bb = lane; bb < cnt; bb += 32) {
                    int t = bb, r = 0;
                    while (t > r) { t -= r + 1; r++; }
                    int c = t;
                    int ri = base + 4 * r, ci = base + 4 * c;
                    bool diag = (r == c);
                    int oR[4], oC[4];
                    oR[0] = toff(ri);
                    oR[1] = oR[0] + ri + 1; oR[2] = oR[1] + ri + 2; oR[3] = oR[2] + ri + 3;
                    oC[0] = toff(ci);
                    oC[1] = oC[0] + ci + 1; oC[2] = oC[1] + ci + 2; oC[3] = oC[2] + ci + 3;
                    u64 a2[4][4];
#pragma unroll
                    for (int a = 0; a < 4; a++)
#pragma unroll
                        for (int cb = 0; cb < 4; cb++)
                            a2[a][cb] = pH2[oR[a] + ci + cb];
#pragma unroll
                    for (int kk = 0; kk < 8; kk++) {
                        u64 nla[4], lb[4];
#pragma unroll
                        for (int a = 0; a < 4; a++) nla[a] = neg2(pH2[oR[a] + k0 + kk]);
#pragma unroll
                        for (int cb = 0; cb < 4; cb++) lb[cb] = pH2[oC[cb] + k0 + kk];
#pragma unroll
                        for (int a = 0; a < 4; a++)
#pragma unroll
                            for (int cb = 0; cb < 4; cb++)
                                a2[a][cb] = fma2(nla[a], lb[cb], a2[a][cb]);
                    }
#pragma unroll
                    for (int a = 0; a < 4; a++)
#pragma unroll
                        for (int cb = 0; cb < 4; cb++)
                            if (!diag || cb <= a) pH2[oR[a] + ci + cb] = a2[a][cb];
                }
                __syncwarp();
            }
        }

        // ---- triangular solves (packed) ----
        {
            int offL0 = toff(lane);
            int offL1 = toff(32 + lane);
            u64 a0 = pR2[lane];
            u64 a1 = (lane < 8) ? pR2[32 + lane] : 0ULL;
            for (int k = 0; k < NU; k++) {
                u64 src = (k < 32) ? a0 : a1;
                u64 y = mul2(__shfl_sync(0xffffffffu, src, k & 31), pLi2[k]);
                if (k < 32) { if (lane == k) a0 = y; }
                else        { if (lane == k - 32) a1 = y; }
                u64 ny = neg2(y);
                if (lane > k) a0 = fma2(pH2[offL0 + k], ny, a0);
                if (lane < 8 && 32 + lane > k) a1 = fma2(pH2[offL1 + k], ny, a1);
            }
            int offk = toff(NU - 1);
            for (int k = NU - 1; k >= 0; k--) {
                u64 src = (k < 32) ? a0 : a1;
                u64 x = mul2(__shfl_sync(0xffffffffu, src, k & 31), pLi2[k]);
                if (k < 32) { if (lane == k) a0 = x; }
                else        { if (lane == k - 32) a1 = x; }
                u64 nx = neg2(x);
                if (lane < k) a0 = fma2(pH2[offk + lane], nx, a0);
                if (lane < 8 && 32 + lane < k) a1 = fma2(pH2[offk + 32 + lane], nx, a1);
                offk -= k;
            }
            pDU2[lane] = a0;
            if (lane < 8) pDU2[32 + lane] = a1;
        }
        __syncwarp();

        // ---- S4: ds, dlam, alpha (sparse dots) ----
        float am0 = BIGF, am1 = BIGF;
        float ds0a[5], ds1a[5], dl0a[5], dl1a[5];
#pragma unroll
        for (int t = 0; t < 5; t++) {
            int j = lane + 32 * t;
            if (j < NINEQ) {
                u64 g;
                if (j < NU) g = pDU2[j];
                else {
                    const float4* br4 = (const float4*)(sB + (j - NU) * 44);
                    u64 acc = 0ULL;
                    int bnd = (t == 1) ? QBND1 : (t == 2) ? QBND2 : (t == 3) ? QBND3 : QBND4;
#pragma unroll
                    for (int q = 0; q < 9; q++) {
                        if (q >= bnd) break;
                        float4 bv = br4[q];
                        acc = fma2(rep2(bv.x), pDU2[4 * q + 0], acc);
                        acc = fma2(rep2(bv.y), pDU2[4 * q + 1], acc);
                        acc = fma2(rep2(bv.z), pDU2[4 * q + 2], acc);
                        acc = fma2(rep2(bv.w), pDU2[4 * q + 3], acc);
                    }
                    g = acc;
                }
                float g0, g1, d0, d1, v0, v1;
                upk2(g, g0, g1);
                upk2(pD2[j], d0, d1);
                upk2(pV2[j], v0, v1);
                float ds0 = -rp0[t] - g0, ds1 = -rp1[t] - g1;
                float dl0 = v0 - rl0[t] + d0 * g0;
                float dl1 = v1 - rl1[t] + d1 * g1;
                ds0a[t] = ds0; ds1a[t] = ds1; dl0a[t] = dl0; dl1a[t] = dl1;
                float q0 = (ds0 < 0.f) ? -rs0[t] / ds0 : BIGF;
                float q1 = (dl0 < 0.f) ? -rl0[t] / dl0 : BIGF;
                am0 = fminf(am0, fminf(q0, q1));
                float q2 = (ds1 < 0.f) ? -rs1[t] / ds1 : BIGF;
                float q3 = (dl1 < 0.f) ? -rl1[t] / dl1 : BIGF;
                am1 = fminf(am1, fminf(q2, q3));
            }
        }
#pragma unroll
        for (int o = 16; o; o >>= 1) {
            am0 = fminf(am0, __shfl_xor_sync(0xffffffffu, am0, o));
            am1 = fminf(am1, __shfl_xor_sync(0xffffffffu, am1, o));
        }
        float al0 = fminf(1.0f, 0.99f * am0);
        float al1 = fminf(1.0f, 0.99f * am1);

        // ---- S5: update + mu ----
        float ls0 = 0.f, ls1 = 0.f;
#pragma unroll
        for (int t = 0; t < 5; t++) {
            int j = lane + 32 * t;
            if (j < NINEQ) {
                rs0[t] += al0 * ds0a[t];  rl0[t] += al0 * dl0a[t];  ls0 += rs0[t] * rl0[t];
                rs1[t] += al1 * ds1a[t];  rl1[t] += al1 * dl1a[t];  ls1 += rs1[t] * rl1[t];
            }
        }
#pragma unroll
        for (int o = 16; o; o >>= 1) {
            ls0 += __shfl_xor_sync(0xffffffffu, ls0, o);
            ls1 += __shfl_xor_sync(0xffffffffu, ls1, o);
        }
        mu0 = ls0 * (1.0f / 148.0f);
        mu1 = ls1 * (1.0f / 148.0f);

        u64 alp = pk2(al0, al1);
        pU2[lane] = fma2(alp, pDU2[lane], pU2[lane]);
        if (lane < 8) pU2[32 + lane] = fma2(alp, pDU2[32 + lane], pU2[32 + lane]);
        __syncwarp();
    }

    // ---- output: Q_value = 0.5 u'Qu + p'u ; u0 ----
    {
        const float4* q0 = (const float4*)(sQ + lane * 44);
        const float4* q1 = (const float4*)(sQ + (32 + lane) * 44);
        u64 qu0 = 0ULL, qu1 = 0ULL;
#pragma unroll
        for (int q = 0; q < 10; q++) {
            float4 qv0 = q0[q];
            qu0 = fma2(rep2(qv0.x), pU2[4 * q + 0], qu0);
            qu0 = fma2(rep2(qv0.y), pU2[4 * q + 1], qu0);
            qu0 = fma2(rep2(qv0.z), pU2[4 * q + 2], qu0);
            qu0 = fma2(rep2(qv0.w), pU2[4 * q + 3], qu0);
            if (lane < 8) {
                float4 qv1 = q1[q];
                qu1 = fma2(rep2(qv1.x), pU2[4 * q + 0], qu1);
                qu1 = fma2(rep2(qv1.y), pU2[4 * q + 1], qu1);
                qu1 = fma2(rep2(qv1.z), pU2[4 * q + 2], qu1);
                qu1 = fma2(rep2(qv1.w), pU2[4 * q + 3], qu1);
            }
        }
        float qa0, qa1, ua0, ua1, pa0, pa1;
        upk2(qu0, qa0, qa1);
        upk2(pU2[lane], ua0, ua1);
        upk2(pP2[lane], pa0, pa1);
        float part0 = ua0 * (0.5f * qa0 + pa0);
        float part1 = ua1 * (0.5f * qa1 + pa1);
        if (lane < 8) {
            float qb0, qb1, ub0, ub1, pb0, pb1;
            upk2(qu1, qb0, qb1);
            upk2(pU2[32 + lane], ub0, ub1);
            upk2(pP2[32 + lane], pb0, pb1);
            part0 += ub0 * (0.5f * qb0 + pb0);
            part1 += ub1 * (0.5f * qb1 + pb1);
        }
#pragma unroll
        for (int o = 16; o; o >>= 1) {
            part0 += __shfl_xor_sync(0xffffffffu, part0, o);
            part1 += __shfl_xor_sync(0xffffffffu, part1, o);
        }
        if (lane == 0) {
            float u00, u01;
            upk2(pU2[0], u00, u01);
            out[pb] = part0;
            out[pb + 1] = part1;
            out[BATCH + pb] = u00;
            out[BATCH + pb + 1] = u01;
        }
    }
}

// ================= launch =================
extern "C" void kernel_launch(void* const* d_in, const int* in_sizes, int n_in,
                              void* d_out, int out_size) {
    const float* x  = (const float*)d_in[0];
    const float* W1 = (const float*)d_in[1];
    const float* b1 = (const float*)d_in[2];
    const float* W2 = (const float*)d_in[3];
    const float* b2 = (const float*)d_in[4];
    const float* L  = (const float*)d_in[5];
    const float* LP = (const float*)d_in[6];
    const float* LR = (const float*)d_in[7];
    const float* A  = (const float*)d_in[8];
    const float* Bm = (const float*)d_in[9];
    const float* u0 = (const float*)d_in[10];
    const float* s0 = (const float*)d_in[11];

    cudaFuncSetAttribute(ipm_kernel, cudaFuncAttributeMaxDynamicSharedMemorySize, SMEM_BYTES);

    setup_kernel<<<1, 128>>>(L, LP, LR, A, Bm, u0, s0);
    mlp_kernel<<<BATCH / 4, 128>>>(x, W1, b1, W2, b2);
    ipm_kernel<<<BATCH / PPC, NTH, SMEM_BYTES>>>((float*)d_out);
}

// round 10
// speedup vs baseline: 1.3370x; 1.1761x over previous
#include <cuda_runtime.h>
#include <math.h>

#define NIN   12
#define NOUT  4
#define NHID  512
#define NU    40
#define NB    108
#define NINEQ 148
#define BATCH 4096
#define IPM_ITERS 20
#define SIGMA 0.1f
#define BIGF  1000000000.0f
#define EPSF  0.0001f

#define WPB   8
#define PPW   2
#define PPC   (WPB * PPW)
#define NTH   (32 * WPB)

// shared scalar layout (floats)
#define SQ_OFF 0                // 40*44 = 1760
#define SB_OFF 1760             // 108*44 = 4752
#define SH_OFF 6512             // 148 -> pad to 6672
#define PR_OFF 6672

// per-pair packed layout (u64 units)
#define H2_OFF   0              // 820 packed lower triangle
#define D2_OFF   820            // 148
#define V2_OFF   968            // 148
#define U2_OFF   1116           // 40
#define RHS2_OFF 1156           // 40
#define DU2_OFF  1196           // 40
#define LDI2_OFF 1236           // 40
#define P2_OFF   1276           // 40
#define PSTRIDE_U64 1320

#define SMEM_FLOATS (PR_OFF + WPB * PSTRIDE_U64 * 2)
#define SMEM_BYTES  (SMEM_FLOATS * 4)

typedef unsigned long long u64;

__device__ __forceinline__ u64 pk2(float lo, float hi) {
    u64 r; asm("mov.b64 %0,{%1,%2};" : "=l"(r) : "f"(lo), "f"(hi)); return r;
}
__device__ __forceinline__ void upk2(u64 v, float& lo, float& hi) {
    asm("mov.b64 {%0,%1},%2;" : "=f"(lo), "=f"(hi) : "l"(v));
}
__device__ __forceinline__ u64 rep2(float x) { return pk2(x, x); }
__device__ __forceinline__ u64 fma2(u64 a, u64 b, u64 c) {
    u64 d; asm("fma.rn.f32x2 %0,%1,%2,%3;" : "=l"(d) : "l"(a), "l"(b), "l"(c)); return d;
}
__device__ __forceinline__ u64 mul2(u64 a, u64 b) {
    u64 d; asm("mul.rn.f32x2 %0,%1,%2;" : "=l"(d) : "l"(a), "l"(b)); return d;
}
__device__ __forceinline__ u64 add2(u64 a, u64 b) {
    u64 d; asm("add.rn.f32x2 %0,%1,%2;" : "=l"(d) : "l"(a), "l"(b)); return d;
}
__device__ __forceinline__ u64 neg2(u64 a) { return a ^ 0x8000000080000000ULL; }

__device__ float g_Q[NU * NU];
__device__ float g_B[NB * NU];
__device__ float g_h[NINEQ];
__device__ float g_p[BATCH * NU];

__device__ __forceinline__ float lrelu(float x) { return x > 0.f ? x : 0.01f * x; }
__device__ __forceinline__ int toff(int r) { return (r * (r + 1)) >> 1; }

// ================= setup =================
__global__ void setup_kernel(const float* __restrict__ L, const float* __restrict__ LP,
                             const float* __restrict__ LR, const float* __restrict__ A,
                             const float* __restrict__ Bm, const float* __restrict__ u0,
                             const float* __restrict__ s0) {
    __shared__ float sQx[144], sP[144], sR[16], sBp[9 * 48];
    __shared__ float sBh[NB * NU];
    __shared__ float sM[NB * NU];
    int tid = threadIdx.x;
    const int NTs = 128;

    for (int idx = tid; idx < 144; idx += NTs) {
        int i = idx / 12, j = idx % 12;
        int mn = i < j ? i : j;
        float a = 0.f, b = 0.f;
        for (int k = 0; k <= mn; k++) {
            a += L[i * 12 + k] * L[j * 12 + k];
            b += LP[i * 12 + k] * LP[j * 12 + k];
        }
        sQx[idx] = a + (i == j ? EPSF : 0.f);
        sP[idx]  = b + (i == j ? EPSF : 0.f);
    }
    for (int idx = tid; idx < 16; idx += NTs) {
        int i = idx / 4, j = idx % 4;
        int mn = i < j ? i : j;
        float a = 0.f;
        for (int k = 0; k <= mn; k++) a += LR[i * 4 + k] * LR[j * 4 + k];
        sR[idx] = a + (i == j ? EPSF : 0.f);
    }
    if (tid < 48) sBp[tid] = Bm[tid];
    __syncthreads();

    for (int m = 1; m < 9; m++) {
        if (tid < 48) {
            int i = tid / 4, o = tid % 4;
            float v = 0.f;
            for (int k = 0; k < 12; k++) v += A[i * 12 + k] * sBp[(m - 1) * 48 + k * 4 + o];
            sBp[m * 48 + tid] = v;
        }
        __syncthreads();
    }

    for (int idx = tid; idx < NB * NU; idx += NTs) {
        int row = idx / NU, col = idx % NU;
        int rb = row / 12, i = row % 12, cb = col / 4, o = col % 4;
        float v = (cb <= rb) ? sBp[(rb - cb) * 48 + i * 4 + o] : 0.f;
        sBh[idx] = v;
        g_B[idx] = v;
    }
    __syncthreads();

    for (int idx = tid; idx < NB * NU; idx += NTs) {
        int row = idx / NU, col = idx % NU;
        int rb = row / 12, i = row % 12;
        const float* Qd = (rb < 8) ? sQx : sP;
        float a = 0.f;
        for (int k = 0; k < 12; k++) a += Qd[i * 12 + k] * sBh[(rb * 12 + k) * NU + col];
        sM[idx] = a;
    }
    __syncthreads();

    for (int idx = tid; idx < NU * NU; idx += NTs) {
        int a_ = idx / NU, b_ = idx % NU;
        float v = (a_ / 4 == b_ / 4) ? sR[(a_ % 4) * 4 + (b_ % 4)] : 0.f;
        for (int r = 0; r < NB; r++) v += sBh[r * NU + a_] * sM[r * NU + b_];
        g_Q[idx] = v;
    }

    for (int j = tid; j < NINEQ; j += NTs) {
        float v = s0[j];
        if (j < NU) v += u0[j];
        else {
            for (int i = 0; i < NU; i++) v += sBh[(j - NU) * NU + i] * u0[i];
        }
        g_h[j] = v;
    }
}

// ================= MLP =================
__global__ void mlp_kernel(const float* __restrict__ x, const float* __restrict__ W1,
                           const float* __restrict__ b1, const float* __restrict__ W2,
                           const float* __restrict__ b2) {
    __shared__ float hbuf[4][NHID];
    int warp = threadIdx.x >> 5, lane = threadIdx.x & 31;
    int row = blockIdx.x * 4 + warp;

    float xr[NIN];
#pragma unroll
    for (int c = 0; c < NIN; c++) xr[c] = x[row * NIN + c];

#pragma unroll
    for (int t = 0; t < NHID / 32; t++) {
        int j = lane + 32 * t;
        const float* w = W1 + j * NIN;
        float acc = b1[j];
#pragma unroll
        for (int c = 0; c < NIN; c++) acc += w[c] * xr[c];
        hbuf[warp][j] = lrelu(acc);
    }
    __syncwarp();

    for (int k = 0; k < NU; k++) {
        const float* w = W2 + k * NHID;
        float acc = 0.f;
#pragma unroll
        for (int t = 0; t < NHID / 32; t++) {
            int j = lane + 32 * t;
            acc += w[j] * hbuf[warp][j];
        }
#pragma unroll
        for (int o = 16; o; o >>= 1) acc += __shfl_xor_sync(0xffffffffu, acc, o);
        if (lane == 0) g_p[row * NU + k] = lrelu(acc + b2[k]);
    }
}

// ================= IPM: two problems per warp, f32x2 =================
__global__ void __launch_bounds__(NTH, 2) ipm_kernel(float* __restrict__ out) {
    extern __shared__ float sm[];
    float* sQ  = sm + SQ_OFF;    // stride 44
    float* sB  = sm + SB_OFF;    // stride 44
    float* sh_ = sm + SH_OFF;

    int tid = threadIdx.x;
    int lane = tid & 31, wid = tid >> 5;

    for (int idx = tid; idx < NU * NU; idx += NTH) sQ[(idx / NU) * 44 + idx % NU] = g_Q[idx];
    for (int idx = tid; idx < NB * NU; idx += NTH) sB[(idx / NU) * 44 + idx % NU] = g_B[idx];
    for (int idx = tid; idx < NINEQ; idx += NTH) sh_[idx] = g_h[idx];
    __syncthreads();

    int pb = blockIdx.x * PPC + wid * PPW;
    u64* PR = (u64*)(sm + PR_OFF) + wid * PSTRIDE_U64;
    u64* pH2  = PR + H2_OFF;
    u64* pD2  = PR + D2_OFF;
    u64* pV2  = PR + V2_OFF;
    u64* pU2  = PR + U2_OFF;
    u64* pR2  = PR + RHS2_OFF;
    u64* pDU2 = PR + DU2_OFF;
    u64* pLi2 = PR + LDI2_OFF;
    u64* pP2  = PR + P2_OFF;

    if (lane < NU) {
        pU2[lane] = 0ULL;
        pP2[lane] = pk2(g_p[pb * NU + lane], g_p[(pb + 1) * NU + lane]);
    }
    if (lane < 8) {
        pU2[32 + lane] = 0ULL;
        pP2[32 + lane] = pk2(g_p[pb * NU + 32 + lane], g_p[(pb + 1) * NU + 32 + lane]);
    }

    // scalar per-lane state
    float rs0[5], rs1[5], rl0[5], rl1[5], rp0[5], rp1[5];
#pragma unroll
    for (int t = 0; t < 5; t++) { rs0[t] = rs1[t] = rl0[t] = rl1[t] = 1.f; }
    float mu0 = 1.0f, mu1 = 1.0f;

    // H 4x4 block-pair assignment (25 pairs + 5 singles, lanes 30,31 idle)
    int bi = 0, bkA = 0, bkB = 0;
    bool hasB = false, active = false;
    {
        int idx = 0;
        for (int r = 0; r < 10; r++) {
            int np = (r + 1) / 2;
            for (int q = 0; q < np; q++) {
                if (idx == lane) { bi = r; bkA = 2 * q; bkB = 2 * q + 1; hasB = true; active = true; }
                idx++;
            }
        }
        for (int r = 0; r < 10; r += 2) {
            if (idx == lane) { bi = r; bkA = r; bkB = r; hasB = false; active = true; }
            idx++;
        }
    }
    bool diagA = (bkA == bi);
    bool diagB = (bkB == bi);

    __syncwarp();

    for (int it = 0; it < IPM_ITERS; it++) {
        // ---- S0: d, rp, v (sparse bounds per t-group) ----
#pragma unroll
        for (int t = 0; t < 5; t++) {
            int j = lane + 32 * t;
            if (j < NINEQ) {
                float A0, A1;
                if (j < NU) upk2(pU2[j], A0, A1);
                else {
                    const float4* br4 = (const float4*)(sB + (j - NU) * 44);
                    u64 acc = 0ULL;
                    const int bnd = (t == 1) ? 2 : (t == 2) ? 5 : (t == 3) ? 8 : 9;
#pragma unroll
                    for (int q = 0; q < bnd; q++) {
                        float4 bv = br4[q];
                        acc = fma2(rep2(bv.x), pU2[4 * q + 0], acc);
                        acc = fma2(rep2(bv.y), pU2[4 * q + 1], acc);
                        acc = fma2(rep2(bv.z), pU2[4 * q + 2], acc);
                        acc = fma2(rep2(bv.w), pU2[4 * q + 3], acc);
                    }
                    upk2(acc, A0, A1);
                }
                float ri0 = __fdividef(1.0f, rs0[t]);
                float ri1 = __fdividef(1.0f, rs1[t]);
                float d0 = rl0[t] * ri0, d1 = rl1[t] * ri1;
                pD2[j] = pk2(d0, d1);
                float hj = sh_[j];
                A0 += rs0[t] - hj;  A1 += rs1[t] - hj;
                rp0[t] = A0;  rp1[t] = A1;
                float v0 = SIGMA * mu0 * ri0 + d0 * A0;
                float v1 = SIGMA * mu1 * ri1 + d1 * A1;
                pV2[j] = pk2(v0, v1);
            }
        }
        __syncwarp();

        // ---- S1: H = Q + diag(d) + B^T diag(d) B  (R5 paired dense loop) ----
        {
            u64 acc0[4][4], acc1[4][4];
#pragma unroll
            for (int a = 0; a < 4; a++) {
                float4 v0 = *(const float4*)(sQ + (4 * bi + a) * 44 + 4 * bkA);
                acc0[a][0] = rep2(v0.x); acc0[a][1] = rep2(v0.y);
                acc0[a][2] = rep2(v0.z); acc0[a][3] = rep2(v0.w);
                float4 v1 = *(const float4*)(sQ + (4 * bi + a) * 44 + 4 * bkB);
                acc1[a][0] = rep2(v1.x); acc1[a][1] = rep2(v1.y);
                acc1[a][2] = rep2(v1.z); acc1[a][3] = rep2(v1.w);
            }
            if (diagA) {
#pragma unroll
                for (int a = 0; a < 4; a++) acc0[a][a] = add2(acc0[a][a], pD2[4 * bi + a]);
            }
            if (diagB) {
#pragma unroll
                for (int a = 0; a < 4; a++) acc1[a][a] = add2(acc1[a][a], pD2[4 * bi + a]);
            }
#pragma unroll 2
            for (int j = 0; j < NB; j++) {
                u64 dp = pD2[NU + j];
                const float* br = sB + j * 44;
                float4 gav = *(const float4*)(br + 4 * bi);
                float4 g0  = *(const float4*)(br + 4 * bkA);
                float4 g1  = *(const float4*)(br + 4 * bkB);
                u64 sa[4];
                sa[0] = mul2(dp, rep2(gav.x)); sa[1] = mul2(dp, rep2(gav.y));
                sa[2] = mul2(dp, rep2(gav.z)); sa[3] = mul2(dp, rep2(gav.w));
                u64 rb0[4] = {rep2(g0.x), rep2(g0.y), rep2(g0.z), rep2(g0.w)};
                u64 rb1[4] = {rep2(g1.x), rep2(g1.y), rep2(g1.z), rep2(g1.w)};
#pragma unroll
                for (int a = 0; a < 4; a++)
#pragma unroll
                    for (int c = 0; c < 4; c++) {
                        acc0[a][c] = fma2(sa[a], rb0[c], acc0[a][c]);
                        acc1[a][c] = fma2(sa[a], rb1[c], acc1[a][c]);
                    }
            }
            if (active) {
#pragma unroll
                for (int a = 0; a < 4; a++) {
                    int ob = toff(4 * bi + a);
#pragma unroll
                    for (int c = 0; c < 4; c++)
                        if (!diagA || c <= a) pH2[ob + 4 * bkA + c] = acc0[a][c];
                    if (hasB) {
#pragma unroll
                        for (int c = 0; c < 4; c++)
                            if (!diagB || c <= a) pH2[ob + 4 * bkB + c] = acc1[a][c];
                    }
                }
            }
        }

        // ---- rhs = -(Qu + p + v[:40] + B^T v[40:]) ----
        {
            u64 A0 = add2(pP2[lane], pV2[lane]);
            u64 A1 = (lane < 8) ? add2(pP2[32 + lane], pV2[32 + lane]) : 0ULL;
            const float4* q0 = (const float4*)(sQ + lane * 44);
            const float4* q1 = (const float4*)(sQ + (32 + lane) * 44);
#pragma unroll
            for (int q = 0; q < 10; q++) {
                float4 qv0 = q0[q];
                A0 = fma2(rep2(qv0.x), pU2[4 * q + 0], A0);
                A0 = fma2(rep2(qv0.y), pU2[4 * q + 1], A0);
                A0 = fma2(rep2(qv0.z), pU2[4 * q + 2], A0);
                A0 = fma2(rep2(qv0.w), pU2[4 * q + 3], A0);
                if (lane < 8) {
                    float4 qv1 = q1[q];
                    A1 = fma2(rep2(qv1.x), pU2[4 * q + 0], A1);
                    A1 = fma2(rep2(qv1.y), pU2[4 * q + 1], A1);
                    A1 = fma2(rep2(qv1.z), pU2[4 * q + 2], A1);
                    A1 = fma2(rep2(qv1.w), pU2[4 * q + 3], A1);
                }
            }
#pragma unroll 2
            for (int j = 0; j < NB; j++) {
                const float* br = sB + j * 44;
                A0 = fma2(rep2(br[lane]), pV2[NU + j], A0);
            }
            // cols 32-35 nonzero only for j >= 96; cols 36-39 are zero rows in B
            if (lane < 8) {
#pragma unroll
                for (int j = 96; j < NB; j++) {
                    const float* br = sB + j * 44;
                    A1 = fma2(rep2(br[32 + lane]), pV2[NU + j], A1);
                }
            }
            pR2[lane] = neg2(A0);
            if (lane < 8) pR2[32 + lane] = neg2(A1);
        }
        __syncwarp();

        // ---- S3: blocked Cholesky (panel=8), packed ----
        for (int pp = 0; pp < 5; pp++) {
            int k0 = 8 * pp;
            for (int kk = 0; kk < 8; kk++) {
                int k = k0 + kk;
                int ok = toff(k);
                float h0, h1;
                upk2(pH2[ok + k], h0, h1);
                float i0 = rsqrtf(h0); i0 = i0 * (1.5f - 0.5f * h0 * i0 * i0);
                float i1 = rsqrtf(h1); i1 = i1 * (1.5f - 0.5f * h1 * i1 * i1);
                u64 ip = pk2(i0, i1);
                if (lane == 0) pLi2[k] = ip;
                int r0 = k + 1 + lane, r1 = r0 + 32;
                int or0 = toff(r0), or1 = toff(r1);
                u64 v0 = 0ULL, v1 = 0ULL;
                if (r0 < NU) { v0 = mul2(pH2[or0 + k], ip); pH2[or0 + k] = v0; }
                if (r1 < NU) { v1 = mul2(pH2[or1 + k], ip); pH2[or1 + k] = v1; }
                __syncwarp();
                for (int j = k + 1; j < k0 + 8; j++) {
                    u64 m = __shfl_sync(0xffffffffu, v0, j - k - 1);
                    u64 nm = neg2(m);
                    if (r0 < NU && r0 >= j) pH2[or0 + j] = fma2(nm, v0, pH2[or0 + j]);
                    if (r1 < NU)            pH2[or1 + j] = fma2(nm, v1, pH2[or1 + j]);
                }
                __syncwarp();
            }
            if (pp < 4) {
                int base = k0 + 8;
                int nbk = (NU - base) >> 2;
                int cnt = nbk * (nbk + 1) / 2;
                for (int bb = lane; bb < cnt; bb += 32) {
                    int t = bb, r = 0;
                    while (t > r) { t -= r + 1; r++; }
                    int c = t;
                    int ri = base + 4 * r, ci = base + 4 * c;
                    bool diag = (r == c);
                    int oR[4], oC[4];
                    oR[0] = toff(ri);
                    oR[1] = oR[0] + ri + 1; oR[2] = oR[1] + ri + 2; oR[3] = oR[2] + ri + 3;
                    oC[0] = toff(ci);
                    oC[1] = oC[0] + ci + 1; oC[2] = oC[1] + ci + 2; oC[3] = oC[2] + ci + 3;
                    u64 a2[4][4];
#pragma unroll
                    for (int a = 0; a < 4; a++)
#pragma unroll
                        for (int cb = 0; cb < 4; cb++)
                            a2[a][cb] = pH2[oR[a] + ci + cb];
#pragma unroll
                    for (int kk = 0; kk < 8; kk++) {
                        u64 nla[4], lb[4];
#pragma unroll
                        for (int a = 0; a < 4; a++) nla[a] = neg2(pH2[oR[a] + k0 + kk]);
#pragma unroll
                        for (int cb = 0; cb < 4; cb++) lb[cb] = pH2[oC[cb] + k0 + kk];
#pragma unroll
                        for (int a = 0; a < 4; a++)
#pragma unroll
                            for (int cb = 0; cb < 4; cb++)
                                a2[a][cb] = fma2(nla[a], lb[cb], a2[a][cb]);
                    }
#pragma unroll
                    for (int a = 0; a < 4; a++)
#pragma unroll
                        for (int cb = 0; cb < 4; cb++)
                            if (!diag || cb <= a) pH2[oR[a] + ci + cb] = a2[a][cb];
                }
                __syncwarp();
            }
        }

        // ---- triangular solves (packed) ----
        {
            int offL0 = toff(lane);
            int offL1 = toff(32 + lane);
            u64 a0 = pR2[lane];
            u64 a1 = (lane < 8) ? pR2[32 + lane] : 0ULL;
            for (int k = 0; k < NU; k++) {
                u64 src = (k < 32) ? a0 : a1;
                u64 y = mul2(__shfl_sync(0xffffffffu, src, k & 31), pLi2[k]);
                if (k < 32) { if (lane == k) a0 = y; }
                else        { if (lane == k - 32) a1 = y; }
                u64 ny = neg2(y);
                if (lane > k) a0 = fma2(pH2[offL0 + k], ny, a0);
                if (lane < 8 && 32 + lane > k) a1 = fma2(pH2[offL1 + k], ny, a1);
            }
            int offk = toff(NU - 1);
            for (int k = NU - 1; k >= 0; k--) {
                u64 src = (k < 32) ? a0 : a1;
                u64 x = mul2(__shfl_sync(0xffffffffu, src, k & 31), pLi2[k]);
                if (k < 32) { if (lane == k) a0 = x; }
                else        { if (lane == k - 32) a1 = x; }
                u64 nx = neg2(x);
                if (lane < k) a0 = fma2(pH2[offk + lane], nx, a0);
                if (lane < 8 && 32 + lane < k) a1 = fma2(pH2[offk + 32 + lane], nx, a1);
                offk -= k;
            }
            pDU2[lane] = a0;
            if (lane < 8) pDU2[32 + lane] = a1;
        }
        __syncwarp();

        // ---- S4: ds, dlam, alpha (sparse bounds + fast div) ----
        float am0 = BIGF, am1 = BIGF;
        float ds0a[5], ds1a[5], dl0a[5], dl1a[5];
#pragma unroll
        for (int t = 0; t < 5; t++) {
            int j = lane + 32 * t;
            if (j < NINEQ) {
                u64 g;
                if (j < NU) g = pDU2[j];
                else {
                    const float4* br4 = (const float4*)(sB + (j - NU) * 44);
                    u64 acc = 0ULL;
                    const int bnd = (t == 1) ? 2 : (t == 2) ? 5 : (t == 3) ? 8 : 9;
#pragma unroll
                    for (int q = 0; q < bnd; q++) {
                        float4 bv = br4[q];
                        acc = fma2(rep2(bv.x), pDU2[4 * q + 0], acc);
                        acc = fma2(rep2(bv.y), pDU2[4 * q + 1], acc);
                        acc = fma2(rep2(bv.z), pDU2[4 * q + 2], acc);
                        acc = fma2(rep2(bv.w), pDU2[4 * q + 3], acc);
                    }
                    g = acc;
                }
                float g0, g1, d0, d1, v0, v1;
                upk2(g, g0, g1);
                upk2(pD2[j], d0, d1);
                upk2(pV2[j], v0, v1);
                float ds0 = -rp0[t] - g0, ds1 = -rp1[t] - g1;
                float dl0 = v0 - rl0[t] + d0 * g0;
                float dl1 = v1 - rl1[t] + d1 * g1;
                ds0a[t] = ds0; ds1a[t] = ds1; dl0a[t] = dl0; dl1a[t] = dl1;
                float q0 = (ds0 < 0.f) ? __fdividef(-rs0[t], ds0) : BIGF;
                float q1 = (dl0 < 0.f) ? __fdividef(-rl0[t], dl0) : BIGF;
                am0 = fminf(am0, fminf(q0, q1));
                float q2 = (ds1 < 0.f) ? __fdividef(-rs1[t], ds1) : BIGF;
                float q3 = (dl1 < 0.f) ? __fdividef(-rl1[t], dl1) : BIGF;
                am1 = fminf(am1, fminf(q2, q3));
            }
        }
#pragma unroll
        for (int o = 16; o; o >>= 1) {
            am0 = fminf(am0, __shfl_xor_sync(0xffffffffu, am0, o));
            am1 = fminf(am1, __shfl_xor_sync(0xffffffffu, am1, o));
        }
        float al0 = fminf(1.0f, 0.99f * am0);
        float al1 = fminf(1.0f, 0.99f * am1);

        // ---- S5: update + mu ----
        float ls0 = 0.f, ls1 = 0.f;
#pragma unroll
        for (int t = 0; t < 5; t++) {
            int j = lane + 32 * t;
            if (j < NINEQ) {
                rs0[t] += al0 * ds0a[t];  rl0[t] += al0 * dl0a[t];  ls0 += rs0[t] * rl0[t];
                rs1[t] += al1 * ds1a[t];  rl1[t] += al1 * dl1a[t];  ls1 += rs1[t] * rl1[t];
            }
        }
#pragma unroll
        for (int o = 16; o; o >>= 1) {
            ls0 += __shfl_xor_sync(0xffffffffu, ls0, o);
            ls1 += __shfl_xor_sync(0xffffffffu, ls1, o);
        }
        mu0 = ls0 * (1.0f / 148.0f);
        mu1 = ls1 * (1.0f / 148.0f);

        u64 alp = pk2(al0, al1);
        pU2[lane] = fma2(alp, pDU2[lane], pU2[lane]);
        if (lane < 8) pU2[32 + lane] = fma2(alp, pDU2[32 + lane], pU2[32 + lane]);
        __syncwarp();
    }

    // ---- output: Q_value = 0.5 u'Qu + p'u ; u0 ----
    {
        const float4* q0 = (const float4*)(sQ + lane * 44);
        const float4* q1 = (const float4*)(sQ + (32 + lane) * 44);
        u64 qu0 = 0ULL, qu1 = 0ULL;
#pragma unroll
        for (int q = 0; q < 10; q++) {
            float4 qv0 = q0[q];
            qu0 = fma2(rep2(qv0.x), pU2[4 * q + 0], qu0);
            qu0 = fma2(rep2(qv0.y), pU2[4 * q + 1], qu0);
            qu0 = fma2(rep2(qv0.z), pU2[4 * q + 2], qu0);
            qu0 = fma2(rep2(qv0.w), pU2[4 * q + 3], qu0);
            if (lane < 8) {
                float4 qv1 = q1[q];
                qu1 = fma2(rep2(qv1.x), pU2[4 * q + 0], qu1);
                qu1 = fma2(rep2(qv1.y), pU2[4 * q + 1], qu1);
                qu1 = fma2(rep2(qv1.z), pU2[4 * q + 2], qu1);
                qu1 = fma2(rep2(qv1.w), pU2[4 * q + 3], qu1);
            }
        }
        float qa0, qa1, ua0, ua1, pa0, pa1;
        upk2(qu0, qa0, qa1);
        upk2(pU2[lane], ua0, ua1);
        upk2(pP2[lane], pa0, pa1);
        float part0 = ua0 * (0.5f * qa0 + pa0);
        float part1 = ua1 * (0.5f * qa1 + pa1);
        if (lane < 8) {
            float qb0, qb1, ub0, ub1, pb0, pb1;
            upk2(qu1, qb0, qb1);
            upk2(pU2[32 + lane], ub0, ub1);
            upk2(pP2[32 + lane], pb0, pb1);
            part0 += ub0 * (0.5f * qb0 + pb0);
            part1 += ub1 * (0.5f * qb1 + pb1);
        }
#pragma unroll
        for (int o = 16; o; o >>= 1) {
            part0 += __shfl_xor_sync(0xffffffffu, part0, o);
            part1 += __shfl_xor_sync(0xffffffffu, part1, o);
        }
        if (lane == 0) {
            float u00, u01;
            upk2(pU2[0], u00, u01);
            out[pb] = part0;
            out[pb + 1] = part1;
            out[BATCH + pb] = u00;
            out[BATCH + pb + 1] = u01;
        }
    }
}

// ================= launch =================
extern "C" void kernel_launch(void* const* d_in, const int* in_sizes, int n_in,
                              void* d_out, int out_size) {
    const float* x  = (const float*)d_in[0];
    const float* W1 = (const float*)d_in[1];
    const float* b1 = (const float*)d_in[2];
    const float* W2 = (const float*)d_in[3];
    const float* b2 = (const float*)d_in[4];
    const float* L  = (const float*)d_in[5];
    const float* LP = (const float*)d_in[6];
    const float* LR = (const float*)d_in[7];
    const float* A  = (const float*)d_in[8];
    const float* Bm = (const float*)d_in[9];
    const float* u0 = (const float*)d_in[10];
    const float* s0 = (const float*)d_in[11];

    cudaFuncSetAttribute(ipm_kernel, cudaFuncAttributeMaxDynamicSharedMemorySize, SMEM_BYTES);

    setup_kernel<<<1, 128>>>(L, LP, LR, A, Bm, u0, s0);
    mlp_kernel<<<BATCH / 4, 128>>>(x, W1, b1, W2, b2);
    ipm_kernel<<<BATCH / PPC, NTH, SMEM_BYTES>>>((float*)d_out);
}

// round 11
// speedup vs baseline: 1.4221x; 1.0636x over previous
#include <cuda_runtime.h>
#include <math.h>

#define NIN   12
#define NOUT  4
#define NHID  512
#define NU    40
#define NB    108
#define NINEQ 148
#define BATCH 4096
#define IPM_ITERS 20
#define SIGMA 0.1f
#define BIGF  1000000000.0f
#define EPSF  0.0001f

#define WPB   8
#define PPW   2
#define PPC   (WPB * PPW)
#define NTH   (32 * WPB)

// shared scalar layout (floats)
#define SQ_OFF 0                // 40*44 = 1760
#define SB_OFF 1760             // 108*44 = 4752
#define SH_OFF 6512             // 148 -> pad to 6672
#define PR_OFF 6672

// per-pair packed layout (u64 units)
#define H2_OFF   0              // 820 packed lower triangle
#define D2_OFF   820            // 148
#define V2_OFF   968            // 148
#define U2_OFF   1116           // 40
#define RHS2_OFF 1156           // 40
#define DU2_OFF  1196           // 40
#define LDI2_OFF 1236           // 40
#define P2_OFF   1276           // 40
#define PSTRIDE_U64 1320

#define SMEM_FLOATS (PR_OFF + WPB * PSTRIDE_U64 * 2)
#define SMEM_BYTES  (SMEM_FLOATS * 4)

typedef unsigned long long u64;

__device__ __forceinline__ u64 pk2(float lo, float hi) {
    u64 r; asm("mov.b64 %0,{%1,%2};" : "=l"(r) : "f"(lo), "f"(hi)); return r;
}
__device__ __forceinline__ void upk2(u64 v, float& lo, float& hi) {
    asm("mov.b64 {%0,%1},%2;" : "=f"(lo), "=f"(hi) : "l"(v));
}
__device__ __forceinline__ u64 rep2(float x) { return pk2(x, x); }
__device__ __forceinline__ u64 fma2(u64 a, u64 b, u64 c) {
    u64 d; asm("fma.rn.f32x2 %0,%1,%2,%3;" : "=l"(d) : "l"(a), "l"(b), "l"(c)); return d;
}
__device__ __forceinline__ u64 mul2(u64 a, u64 b) {
    u64 d; asm("mul.rn.f32x2 %0,%1,%2;" : "=l"(d) : "l"(a), "l"(b)); return d;
}
__device__ __forceinline__ u64 add2(u64 a, u64 b) {
    u64 d; asm("add.rn.f32x2 %0,%1,%2;" : "=l"(d) : "l"(a), "l"(b)); return d;
}
__device__ __forceinline__ u64 neg2(u64 a) { return a ^ 0x8000000080000000ULL; }

__device__ float g_Q[NU * NU];
__device__ float g_B[NB * NU];
__device__ float g_h[NINEQ];
__device__ float g_p[BATCH * NU];

__device__ __forceinline__ float lrelu(float x) { return x > 0.f ? x : 0.01f * x; }
__device__ __forceinline__ int toff(int r) { return (r * (r + 1)) >> 1; }

// ================= setup =================
__global__ void setup_kernel(const float* __restrict__ L, const float* __restrict__ LP,
                             const float* __restrict__ LR, const float* __restrict__ A,
                             const float* __restrict__ Bm, const float* __restrict__ u0,
                             const float* __restrict__ s0) {
    __shared__ float sQx[144], sP[144], sR[16], sBp[9 * 48];
    __shared__ float sBh[NB * NU];
    __shared__ float sM[NB * NU];
    int tid = threadIdx.x;
    const int NTs = 128;

    for (int idx = tid; idx < 144; idx += NTs) {
        int i = idx / 12, j = idx % 12;
        int mn = i < j ? i : j;
        float a = 0.f, b = 0.f;
        for (int k = 0; k <= mn; k++) {
            a += L[i * 12 + k] * L[j * 12 + k];
            b += LP[i * 12 + k] * LP[j * 12 + k];
        }
        sQx[idx] = a + (i == j ? EPSF : 0.f);
        sP[idx]  = b + (i == j ? EPSF : 0.f);
    }
    for (int idx = tid; idx < 16; idx += NTs) {
        int i = idx / 4, j = idx % 4;
        int mn = i < j ? i : j;
        float a = 0.f;
        for (int k = 0; k <= mn; k++) a += LR[i * 4 + k] * LR[j * 4 + k];
        sR[idx] = a + (i == j ? EPSF : 0.f);
    }
    if (tid < 48) sBp[tid] = Bm[tid];
    __syncthreads();

    for (int m = 1; m < 9; m++) {
        if (tid < 48) {
            int i = tid / 4, o = tid % 4;
            float v = 0.f;
            for (int k = 0; k < 12; k++) v += A[i * 12 + k] * sBp[(m - 1) * 48 + k * 4 + o];
            sBp[m * 48 + tid] = v;
        }
        __syncthreads();
    }

    for (int idx = tid; idx < NB * NU; idx += NTs) {
        int row = idx / NU, col = idx % NU;
        int rb = row / 12, i = row % 12, cb = col / 4, o = col % 4;
        float v = (cb <= rb) ? sBp[(rb - cb) * 48 + i * 4 + o] : 0.f;
        sBh[idx] = v;
        g_B[idx] = v;
    }
    __syncthreads();

    for (int idx = tid; idx < NB * NU; idx += NTs) {
        int row = idx / NU, col = idx % NU;
        int rb = row / 12, i = row % 12;
        const float* Qd = (rb < 8) ? sQx : sP;
        float a = 0.f;
        for (int k = 0; k < 12; k++) a += Qd[i * 12 + k] * sBh[(rb * 12 + k) * NU + col];
        sM[idx] = a;
    }
    __syncthreads();

    for (int idx = tid; idx < NU * NU; idx += NTs) {
        int a_ = idx / NU, b_ = idx % NU;
        float v = (a_ / 4 == b_ / 4) ? sR[(a_ % 4) * 4 + (b_ % 4)] : 0.f;
        for (int r = 0; r < NB; r++) v += sBh[r * NU + a_] * sM[r * NU + b_];
        g_Q[idx] = v;
    }

    for (int j = tid; j < NINEQ; j += NTs) {
        float v = s0[j];
        if (j < NU) v += u0[j];
        else {
            for (int i = 0; i < NU; i++) v += sBh[(j - NU) * NU + i] * u0[i];
        }
        g_h[j] = v;
    }
}

// ================= MLP =================
__global__ void mlp_kernel(const float* __restrict__ x, const float* __restrict__ W1,
                           const float* __restrict__ b1, const float* __restrict__ W2,
                           const float* __restrict__ b2) {
    __shared__ float hbuf[4][NHID];
    int warp = threadIdx.x >> 5, lane = threadIdx.x & 31;
    int row = blockIdx.x * 4 + warp;

    float xr[NIN];
#pragma unroll
    for (int c = 0; c < NIN; c++) xr[c] = x[row * NIN + c];

#pragma unroll
    for (int t = 0; t < NHID / 32; t++) {
        int j = lane + 32 * t;
        const float* w = W1 + j * NIN;
        float acc = b1[j];
#pragma unroll
        for (int c = 0; c < NIN; c++) acc += w[c] * xr[c];
        hbuf[warp][j] = lrelu(acc);
    }
    __syncwarp();

    for (int k = 0; k < NU; k++) {
        const float* w = W2 + k * NHID;
        float acc = 0.f;
#pragma unroll
        for (int t = 0; t < NHID / 32; t++) {
            int j = lane + 32 * t;
            acc += w[j] * hbuf[warp][j];
        }
#pragma unroll
        for (int o = 16; o; o >>= 1) acc += __shfl_xor_sync(0xffffffffu, acc, o);
        if (lane == 0) g_p[row * NU + k] = lrelu(acc + b2[k]);
    }
}

// ================= IPM: two problems per warp, f32x2 =================
__global__ void __launch_bounds__(NTH, 2) ipm_kernel(float* __restrict__ out) {
    extern __shared__ float sm[];
    float* sQ  = sm + SQ_OFF;    // stride 44
    float* sB  = sm + SB_OFF;    // stride 44
    float* sh_ = sm + SH_OFF;

    int tid = threadIdx.x;
    int lane = tid & 31, wid = tid >> 5;

    for (int idx = tid; idx < NU * NU; idx += NTH) sQ[(idx / NU) * 44 + idx % NU] = g_Q[idx];
    for (int idx = tid; idx < NB * NU; idx += NTH) sB[(idx / NU) * 44 + idx % NU] = g_B[idx];
    for (int idx = tid; idx < NINEQ; idx += NTH) sh_[idx] = g_h[idx];
    __syncthreads();

    int pb = blockIdx.x * PPC + wid * PPW;
    u64* PR = (u64*)(sm + PR_OFF) + wid * PSTRIDE_U64;
    u64* pH2  = PR + H2_OFF;
    u64* pD2  = PR + D2_OFF;
    u64* pV2  = PR + V2_OFF;
    u64* pU2  = PR + U2_OFF;
    u64* pR2  = PR + RHS2_OFF;
    u64* pDU2 = PR + DU2_OFF;
    u64* pLi2 = PR + LDI2_OFF;
    u64* pP2  = PR + P2_OFF;

    if (lane < NU) {
        pU2[lane] = 0ULL;
        pP2[lane] = pk2(g_p[pb * NU + lane], g_p[(pb + 1) * NU + lane]);
    }
    if (lane < 8) {
        pU2[32 + lane] = 0ULL;
        pP2[32 + lane] = pk2(g_p[pb * NU + 32 + lane], g_p[(pb + 1) * NU + 32 + lane]);
    }

    // scalar per-lane state
    float rs0[5], rs1[5], rl0[5], rl1[5], rp0[5], rp1[5];
#pragma unroll
    for (int t = 0; t < 5; t++) { rs0[t] = rs1[t] = rl0[t] = rl1[t] = 1.f; }
    float mu0 = 1.0f, mu1 = 1.0f;

    // H 4x4 block-pair assignment (25 pairs + 5 singles, lanes 30,31 idle)
    int bi = 0, bkA = 0, bkB = 0;
    bool hasB = false, active = false;
    {
        int idx = 0;
        for (int r = 0; r < 10; r++) {
            int np = (r + 1) / 2;
            for (int q = 0; q < np; q++) {
                if (idx == lane) { bi = r; bkA = 2 * q; bkB = 2 * q + 1; hasB = true; active = true; }
                idx++;
            }
        }
        for (int r = 0; r < 10; r += 2) {
            if (idx == lane) { bi = r; bkA = r; bkB = r; hasB = false; active = true; }
            idx++;
        }
    }
    bool diagA = (bkA == bi);
    bool diagB = (bkB == bi);

    __syncwarp();

    for (int it = 0; it < IPM_ITERS; it++) {
        // ---- S0: d, rp, v (sparse bounds per t-group) ----
#pragma unroll
        for (int t = 0; t < 5; t++) {
            int j = lane + 32 * t;
            if (j < NINEQ) {
                float A0, A1;
                if (j < NU) upk2(pU2[j], A0, A1);
                else {
                    const float4* br4 = (const float4*)(sB + (j - NU) * 44);
                    u64 acc = 0ULL;
                    const int bnd = (t == 1) ? 2 : (t == 2) ? 5 : (t == 3) ? 8 : 9;
#pragma unroll
                    for (int q = 0; q < bnd; q++) {
                        float4 bv = br4[q];
                        acc = fma2(rep2(bv.x), pU2[4 * q + 0], acc);
                        acc = fma2(rep2(bv.y), pU2[4 * q + 1], acc);
                        acc = fma2(rep2(bv.z), pU2[4 * q + 2], acc);
                        acc = fma2(rep2(bv.w), pU2[4 * q + 3], acc);
                    }
                    upk2(acc, A0, A1);
                }
                float ri0 = __fdividef(1.0f, rs0[t]);
                float ri1 = __fdividef(1.0f, rs1[t]);
                float d0 = rl0[t] * ri0, d1 = rl1[t] * ri1;
                pD2[j] = pk2(d0, d1);
                float hj = sh_[j];
                A0 += rs0[t] - hj;  A1 += rs1[t] - hj;
                rp0[t] = A0;  rp1[t] = A1;
                float v0 = SIGMA * mu0 * ri0 + d0 * A0;
                float v1 = SIGMA * mu1 * ri1 + d1 * A1;
                pV2[j] = pk2(v0, v1);
            }
        }
        __syncwarp();

        // ---- S1: H = Q + diag(d) + B^T diag(d) B  (paired dense loop) ----
        {
            u64 acc0[4][4], acc1[4][4];
#pragma unroll
            for (int a = 0; a < 4; a++) {
                float4 v0 = *(const float4*)(sQ + (4 * bi + a) * 44 + 4 * bkA);
                acc0[a][0] = rep2(v0.x); acc0[a][1] = rep2(v0.y);
                acc0[a][2] = rep2(v0.z); acc0[a][3] = rep2(v0.w);
                float4 v1 = *(const float4*)(sQ + (4 * bi + a) * 44 + 4 * bkB);
                acc1[a][0] = rep2(v1.x); acc1[a][1] = rep2(v1.y);
                acc1[a][2] = rep2(v1.z); acc1[a][3] = rep2(v1.w);
            }
            if (diagA) {
#pragma unroll
                for (int a = 0; a < 4; a++) acc0[a][a] = add2(acc0[a][a], pD2[4 * bi + a]);
            }
            if (diagB) {
#pragma unroll
                for (int a = 0; a < 4; a++) acc1[a][a] = add2(acc1[a][a], pD2[4 * bi + a]);
            }
#pragma unroll 2
            for (int j = 0; j < NB; j++) {
                u64 dp = pD2[NU + j];
                const float* br = sB + j * 44;
                float4 gav = *(const float4*)(br + 4 * bi);
                float4 g0  = *(const float4*)(br + 4 * bkA);
                float4 g1  = *(const float4*)(br + 4 * bkB);
                u64 sa[4];
                sa[0] = mul2(dp, rep2(gav.x)); sa[1] = mul2(dp, rep2(gav.y));
                sa[2] = mul2(dp, rep2(gav.z)); sa[3] = mul2(dp, rep2(gav.w));
                u64 rb0[4] = {rep2(g0.x), rep2(g0.y), rep2(g0.z), rep2(g0.w)};
                u64 rb1[4] = {rep2(g1.x), rep2(g1.y), rep2(g1.z), rep2(g1.w)};
#pragma unroll
                for (int a = 0; a < 4; a++)
#pragma unroll
                    for (int c = 0; c < 4; c++) {
                        acc0[a][c] = fma2(sa[a], rb0[c], acc0[a][c]);
                        acc1[a][c] = fma2(sa[a], rb1[c], acc1[a][c]);
                    }
            }
            if (active) {
#pragma unroll
                for (int a = 0; a < 4; a++) {
                    int ob = toff(4 * bi + a);
#pragma unroll
                    for (int c = 0; c < 4; c++)
                        if (!diagA || c <= a) pH2[ob + 4 * bkA + c] = acc0[a][c];
                    if (hasB) {
#pragma unroll
                        for (int c = 0; c < 4; c++)
                            if (!diagB || c <= a) pH2[ob + 4 * bkB + c] = acc1[a][c];
                    }
                }
            }
        }

        // ---- rhs = -(Qu + p + v[:40] + B^T v[40:]) ----
        {
            u64 A0 = add2(pP2[lane], pV2[lane]);
            u64 A1 = (lane < 8) ? add2(pP2[32 + lane], pV2[32 + lane]) : 0ULL;
            const float4* q0 = (const float4*)(sQ + lane * 44);
            const float4* q1 = (const float4*)(sQ + (32 + lane) * 44);
#pragma unroll
            for (int q = 0; q < 10; q++) {
                float4 qv0 = q0[q];
                A0 = fma2(rep2(qv0.x), pU2[4 * q + 0], A0);
                A0 = fma2(rep2(qv0.y), pU2[4 * q + 1], A0);
                A0 = fma2(rep2(qv0.z), pU2[4 * q + 2], A0);
                A0 = fma2(rep2(qv0.w), pU2[4 * q + 3], A0);
                if (lane < 8) {
                    float4 qv1 = q1[q];
                    A1 = fma2(rep2(qv1.x), pU2[4 * q + 0], A1);
                    A1 = fma2(rep2(qv1.y), pU2[4 * q + 1], A1);
                    A1 = fma2(rep2(qv1.z), pU2[4 * q + 2], A1);
                    A1 = fma2(rep2(qv1.w), pU2[4 * q + 3], A1);
                }
            }
#pragma unroll 2
            for (int j = 0; j < NB; j++) {
                const float* br = sB + j * 44;
                A0 = fma2(rep2(br[lane]), pV2[NU + j], A0);
            }
            // cols 32-35 nonzero only for j >= 96; cols 36-39 are zero rows in B
            if (lane < 8) {
#pragma unroll
                for (int j = 96; j < NB; j++) {
                    const float* br = sB + j * 44;
                    A1 = fma2(rep2(br[32 + lane]), pV2[NU + j], A1);
                }
            }
            pR2[lane] = neg2(A0);
            if (lane < 8) pR2[32 + lane] = neg2(A1);
        }
        __syncwarp();

        // ---- S3: blocked Cholesky (panel=8), packed; 1 syncwarp per k ----
        for (int pp = 0; pp < 5; pp++) {
            int k0 = 8 * pp;
            for (int kk = 0; kk < 8; kk++) {
                int k = k0 + kk;
                int ok = toff(k);
                float h0, h1;
                upk2(pH2[ok + k], h0, h1);
                float i0 = rsqrtf(h0);
                float i1 = rsqrtf(h1);
                u64 ip = pk2(i0, i1);
                if (lane == 0) pLi2[k] = ip;
                int r0 = k + 1 + lane, r1 = r0 + 32;
                int or0 = toff(r0), or1 = toff(r1);
                u64 v0 = 0ULL, v1 = 0ULL;
                if (r0 < NU) { v0 = mul2(pH2[or0 + k], ip); pH2[or0 + k] = v0; }
                if (r1 < NU) { v1 = mul2(pH2[or1 + k], ip); pH2[or1 + k] = v1; }
                // no cross-lane memory dependence inside the j-loop (shfl carries
                // the multiplier; each lane updates only its own rows)
                for (int j = k + 1; j < k0 + 8; j++) {
                    u64 m = __shfl_sync(0xffffffffu, v0, j - k - 1);
                    u64 nm = neg2(m);
                    if (r0 < NU && r0 >= j) pH2[or0 + j] = fma2(nm, v0, pH2[or0 + j]);
                    if (r1 < NU)            pH2[or1 + j] = fma2(nm, v1, pH2[or1 + j]);
                }
                __syncwarp();   // protects next k's diagonal broadcast load
            }
            if (pp < 4) {
                int base = k0 + 8;
                int nbk = (NU - base) >> 2;
                int cnt = nbk * (nbk + 1) / 2;
                for (int bb = lane; bb < cnt; bb += 32) {
                    int t = bb, r = 0;
                    while (t > r) { t -= r + 1; r++; }
                    int c = t;
                    int ri = base + 4 * r, ci = base + 4 * c;
                    bool diag = (r == c);
                    int oR[4], oC[4];
                    oR[0] = toff(ri);
                    oR[1] = oR[0] + ri + 1; oR[2] = oR[1] + ri + 2; oR[3] = oR[2] + ri + 3;
                    oC[0] = toff(ci);
                    oC[1] = oC[0] + ci + 1; oC[2] = oC[1] + ci + 2; oC[3] = oC[2] + ci + 3;
                    u64 a2[4][4];
#pragma unroll
                    for (int a = 0; a < 4; a++)
#pragma unroll
                        for (int cb = 0; cb < 4; cb++)
                            a2[a][cb] = pH2[oR[a] + ci + cb];
#pragma unroll
                    for (int kk = 0; kk < 8; kk++) {
                        u64 nla[4], lb[4];
#pragma unroll
                        for (int a = 0; a < 4; a++) nla[a] = neg2(pH2[oR[a] + k0 + kk]);
#pragma unroll
                        for (int cb = 0; cb < 4; cb++) lb[cb] = pH2[oC[cb] + k0 + kk];
#pragma unroll
                        for (int a = 0; a < 4; a++)
#pragma unroll
                            for (int cb = 0; cb < 4; cb++)
                                a2[a][cb] = fma2(nla[a], lb[cb], a2[a][cb]);
                    }
#pragma unroll
                    for (int a = 0; a < 4; a++)
#pragma unroll
                        for (int cb = 0; cb < 4; cb++)
                            if (!diag || cb <= a) pH2[oR[a] + ci + cb] = a2[a][cb];
                }
                __syncwarp();
            }
        }

        // ---- triangular solves (packed, fully unrolled) ----
        {
            int offL0 = toff(lane);
            int offL1 = toff(32 + lane);
            u64 a0 = pR2[lane];
            u64 a1 = (lane < 8) ? pR2[32 + lane] : 0ULL;
#pragma unroll
            for (int k = 0; k < NU; k++) {
                u64 src = (k < 32) ? a0 : a1;
                u64 y = mul2(__shfl_sync(0xffffffffu, src, k & 31), pLi2[k]);
                if (k < 32) { if (lane == k) a0 = y; }
                else        { if (lane == k - 32) a1 = y; }
                u64 ny = neg2(y);
                if (lane > k) a0 = fma2(pH2[offL0 + k], ny, a0);
                if (lane < 8 && 32 + lane > k) a1 = fma2(pH2[offL1 + k], ny, a1);
            }
#pragma unroll
            for (int k = NU - 1; k >= 0; k--) {
                const int offk = toff(k);
                u64 src = (k < 32) ? a0 : a1;
                u64 x = mul2(__shfl_sync(0xffffffffu, src, k & 31), pLi2[k]);
                if (k < 32) { if (lane == k) a0 = x; }
                else        { if (lane == k - 32) a1 = x; }
                u64 nx = neg2(x);
                if (lane < k) a0 = fma2(pH2[offk + lane], nx, a0);
                if (lane < 8 && 32 + lane < k) a1 = fma2(pH2[offk + 32 + lane], nx, a1);
            }
            pDU2[lane] = a0;
            if (lane < 8) pDU2[32 + lane] = a1;
        }
        __syncwarp();

        // ---- S4: ds, dlam, alpha (sparse bounds + fast div) ----
        float am0 = BIGF, am1 = BIGF;
        float ds0a[5], ds1a[5], dl0a[5], dl1a[5];
#pragma unroll
        for (int t = 0; t < 5; t++) {
            int j = lane + 32 * t;
            if (j < NINEQ) {
                u64 g;
                if (j < NU) g = pDU2[j];
                else {
                    const float4* br4 = (const float4*)(sB + (j - NU) * 44);
                    u64 acc = 0ULL;
                    const int bnd = (t == 1) ? 2 : (t == 2) ? 5 : (t == 3) ? 8 : 9;
#pragma unroll
                    for (int q = 0; q < bnd; q++) {
                        float4 bv = br4[q];
                        acc = fma2(rep2(bv.x), pDU2[4 * q + 0], acc);
                        acc = fma2(rep2(bv.y), pDU2[4 * q + 1], acc);
                        acc = fma2(rep2(bv.z), pDU2[4 * q + 2], acc);
                        acc = fma2(rep2(bv.w), pDU2[4 * q + 3], acc);
                    }
                    g = acc;
                }
                float g0, g1, d0, d1, v0, v1;
                upk2(g, g0, g1);
                upk2(pD2[j], d0, d1);
                upk2(pV2[j], v0, v1);
                float ds0 = -rp0[t] - g0, ds1 = -rp1[t] - g1;
                float dl0 = v0 - rl0[t] + d0 * g0;
                float dl1 = v1 - rl1[t] + d1 * g1;
                ds0a[t] = ds0; ds1a[t] = ds1; dl0a[t] = dl0; dl1a[t] = dl1;
                float q0 = (ds0 < 0.f) ? __fdividef(-rs0[t], ds0) : BIGF;
                float q1 = (dl0 < 0.f) ? __fdividef(-rl0[t], dl0) : BIGF;
                am0 = fminf(am0, fminf(q0, q1));
                float q2 = (ds1 < 0.f) ? __fdividef(-rs1[t], ds1) : BIGF;
                float q3 = (dl1 < 0.f) ? __fdividef(-rl1[t], dl1) : BIGF;
                am1 = fminf(am1, fminf(q2, q3));
            }
        }
#pragma unroll
        for (int o = 16; o; o >>= 1) {
            am0 = fminf(am0, __shfl_xor_sync(0xffffffffu, am0, o));
            am1 = fminf(am1, __shfl_xor_sync(0xffffffffu, am1, o));
        }
        float al0 = fminf(1.0f, 0.99f * am0);
        float al1 = fminf(1.0f, 0.99f * am1);

        // ---- S5: update + mu ----
        float ls0 = 0.f, ls1 = 0.f;
#pragma unroll
        for (int t = 0; t < 5; t++) {
            int j = lane + 32 * t;
            if (j < NINEQ) {
                rs0[t] += al0 * ds0a[t];  rl0[t] += al0 * dl0a[t];  ls0 += rs0[t] * rl0[t];
                rs1[t] += al1 * ds1a[t];  rl1[t] += al1 * dl1a[t];  ls1 += rs1[t] * rl1[t];
            }
        }
#pragma unroll
        for (int o = 16; o; o >>= 1) {
            ls0 += __shfl_xor_sync(0xffffffffu, ls0, o);
            ls1 += __shfl_xor_sync(0xffffffffu, ls1, o);
        }
        mu0 = ls0 * (1.0f / 148.0f);
        mu1 = ls1 * (1.0f / 148.0f);

        u64 alp = pk2(al0, al1);
        pU2[lane] = fma2(alp, pDU2[lane], pU2[lane]);
        if (lane < 8) pU2[32 + lane] = fma2(alp, pDU2[32 + lane], pU2[32 + lane]);
        __syncwarp();
    }

    // ---- output: Q_value = 0.5 u'Qu + p'u ; u0 ----
    {
        const float4* q0 = (const float4*)(sQ + lane * 44);
        const float4* q1 = (const float4*)(sQ + (32 + lane) * 44);
        u64 qu0 = 0ULL, qu1 = 0ULL;
#pragma unroll
        for (int q = 0; q < 10; q++) {
            float4 qv0 = q0[q];
            qu0 = fma2(rep2(qv0.x), pU2[4 * q + 0], qu0);
            qu0 = fma2(rep2(qv0.y), pU2[4 * q + 1], qu0);
            qu0 = fma2(rep2(qv0.z), pU2[4 * q + 2], qu0);
            qu0 = fma2(rep2(qv0.w), pU2[4 * q + 3], qu0);
            if (lane < 8) {
                float4 qv1 = q1[q];
                qu1 = fma2(rep2(qv1.x), pU2[4 * q + 0], qu1);
                qu1 = fma2(rep2(qv1.y), pU2[4 * q + 1], qu1);
                qu1 = fma2(rep2(qv1.z), pU2[4 * q + 2], qu1);
                qu1 = fma2(rep2(qv1.w), pU2[4 * q + 3], qu1);
            }
        }
        float qa0, qa1, ua0, ua1, pa0, pa1;
        upk2(qu0, qa0, qa1);
        upk2(pU2[lane], ua0, ua1);
        upk2(pP2[lane], pa0, pa1);
        float part0 = ua0 * (0.5f * qa0 + pa0);
        float part1 = ua1 * (0.5f * qa1 + pa1);
        if (lane < 8) {
            float qb0, qb1, ub0, ub1, pb0, pb1;
            upk2(qu1, qb0, qb1);
            upk2(pU2[32 + lane], ub0, ub1);
            upk2(pP2[32 + lane], pb0, pb1);
            part0 += ub0 * (0.5f * qb0 + pb0);
            part1 += ub1 * (0.5f * qb1 + pb1);
        }
#pragma unroll
        for (int o = 16; o; o >>= 1) {
            part0 += __shfl_xor_sync(0xffffffffu, part0, o);
            part1 += __shfl_xor_sync(0xffffffffu, part1, o);
        }
        if (lane == 0) {
            float u00, u01;
            upk2(pU2[0], u00, u01);
            out[pb] = part0;
            out[pb + 1] = part1;
            out[BATCH + pb] = u00;
            out[BATCH + pb + 1] = u01;
        }
    }
}

// ================= launch =================
extern "C" void kernel_launch(void* const* d_in, const int* in_sizes, int n_in,
                              void* d_out, int out_size) {
    const float* x  = (const float*)d_in[0];
    const float* W1 = (const float*)d_in[1];
    const float* b1 = (const float*)d_in[2];
    const float* W2 = (const float*)d_in[3];
    const float* b2 = (const float*)d_in[4];
    const float* L  = (const float*)d_in[5];
    const float* LP = (const float*)d_in[6];
    const float* LR = (const float*)d_in[7];
    const float* A  = (const float*)d_in[8];
    const float* Bm = (const float*)d_in[9];
    const float* u0 = (const float*)d_in[10];
    const float* s0 = (const float*)d_in[11];

    cudaFuncSetAttribute(ipm_kernel, cudaFuncAttributeMaxDynamicSharedMemorySize, SMEM_BYTES);

    setup_kernel<<<1, 128>>>(L, LP, LR, A, Bm, u0, s0);
    mlp_kernel<<<BATCH / 4, 128>>>(x, W1, b1, W2, b2);
    ipm_kernel<<<BATCH / PPC, NTH, SMEM_BYTES>>>((float*)d_out);
}